// round 1
// baseline (speedup 1.0000x reference)
#include <cuda_runtime.h>

#define HID 256
#define NB 4096
#define NTOT 131072
#define MAXNB 64

// Scratch (allocation-free rule: __device__ globals)
__device__ float g_Q[(size_t)NB * HID];
__device__ float g_K[(size_t)NTOT * HID];
__device__ float g_V[(size_t)NTOT * HID];
__device__ float g_O[(size_t)NB * HID];

// ---- packed f32x2 helpers (Blackwell) ----
__device__ __forceinline__ unsigned long long pk2(float x, float y) {
    unsigned long long r;
    asm("mov.b64 %0,{%1,%2};" : "=l"(r) : "f"(x), "f"(y));
    return r;
}
__device__ __forceinline__ void upk2(unsigned long long v, float& x, float& y) {
    asm("mov.b64 {%0,%1},%2;" : "=f"(x), "=f"(y) : "l"(v));
}
__device__ __forceinline__ void ffma2(unsigned long long& d, unsigned long long a, unsigned long long b) {
    asm("fma.rn.f32x2 %0,%1,%2,%0;" : "+l"(d) : "l"(a), "l"(b));
}

// C[M,256] = act(A[M,256] @ W[256,256]^T + bias) * scale
// BM=128, BN=128, BK=16, 256 threads, 8x8 per thread (packed pairs over cols)
__global__ __launch_bounds__(256, 2) void gemm256(
    const float* __restrict__ A, const float* __restrict__ W,
    const float* __restrict__ bias, float* __restrict__ C,
    int doRelu, float scale)
{
    __shared__ float As[16][128];
    __shared__ float Bs[16][128];

    const int tid = threadIdx.x;
    const int bm = blockIdx.y, bn = blockIdx.x;
    const int tx = tid & 15, ty = tid >> 4;
    const int r0 = tid >> 2, c0 = (tid & 3) << 2;

    const float* Ag = A + (size_t)(bm * 128 + r0) * HID + c0;
    const float* Wg = W + (size_t)(bn * 128 + r0) * HID + c0;

    unsigned long long acc[8][4];
#pragma unroll
    for (int i = 0; i < 8; i++)
#pragma unroll
        for (int j = 0; j < 4; j++) acc[i][j] = 0ull;

    for (int kt = 0; kt < 16; kt++) {
        const int k0 = kt * 16;
#pragma unroll
        for (int p = 0; p < 2; p++) {
            float4 av = *(const float4*)(Ag + (size_t)p * 64 * HID + k0);
            float4 wv = *(const float4*)(Wg + (size_t)p * 64 * HID + k0);
            As[c0 + 0][r0 + p * 64] = av.x;
            As[c0 + 1][r0 + p * 64] = av.y;
            As[c0 + 2][r0 + p * 64] = av.z;
            As[c0 + 3][r0 + p * 64] = av.w;
            Bs[c0 + 0][r0 + p * 64] = wv.x;
            Bs[c0 + 1][r0 + p * 64] = wv.y;
            Bs[c0 + 2][r0 + p * 64] = wv.z;
            Bs[c0 + 3][r0 + p * 64] = wv.w;
        }
        __syncthreads();
#pragma unroll
        for (int kk = 0; kk < 16; kk++) {
            float a[8];
            *(float4*)&a[0] = *(const float4*)&As[kk][ty * 8];
            *(float4*)&a[4] = *(const float4*)&As[kk][ty * 8 + 4];
            unsigned long long bb[4];
#pragma unroll
            for (int j = 0; j < 4; j++)
                bb[j] = *(const unsigned long long*)&Bs[kk][tx * 8 + 2 * j];
#pragma unroll
            for (int i = 0; i < 8; i++) {
                unsigned long long aa = pk2(a[i], a[i]);
#pragma unroll
                for (int j = 0; j < 4; j++) ffma2(acc[i][j], aa, bb[j]);
            }
        }
        __syncthreads();
    }

    const int col = bn * 128 + tx * 8;
    float bv[8];
#pragma unroll
    for (int j = 0; j < 8; j++) bv[j] = bias[col + j];

#pragma unroll
    for (int i = 0; i < 8; i++) {
        float out[8];
#pragma unroll
        for (int j = 0; j < 4; j++) {
            float x, y;
            upk2(acc[i][j], x, y);
            out[2 * j] = x + bv[2 * j];
            out[2 * j + 1] = y + bv[2 * j + 1];
        }
        if (doRelu) {
#pragma unroll
            for (int j = 0; j < 8; j++) out[j] = fmaxf(out[j], 0.0f);
        }
#pragma unroll
        for (int j = 0; j < 8; j++) out[j] *= scale;
        const int row = bm * 128 + ty * 8 + i;
        *(float4*)&C[(size_t)row * HID + col] = make_float4(out[0], out[1], out[2], out[3]);
        *(float4*)&C[(size_t)row * HID + col + 4] = make_float4(out[4], out[5], out[6], out[7]);
    }
}

// Per-sample attention. 1 CTA / sample, 256 threads.
// smem: Ks[64][257], Vs[64][257], qs[256], sc[256]  (stride 257 => conflict-free)
#define KS_STRIDE 257
__global__ __launch_bounds__(256) void attn_kernel(
    const float* __restrict__ Q, const float* __restrict__ K,
    const float* __restrict__ V, const int* __restrict__ starts,
    const int* __restrict__ ends, float* __restrict__ O)
{
    extern __shared__ float sm[];
    float* Ks = sm;                       // 64*257
    float* Vs = Ks + 64 * KS_STRIDE;      // 64*257
    float* qs = Vs + 64 * KS_STRIDE;      // 256
    float* sc = qs + 256;                 // 256

    const int tid = threadIdx.x;
    const int b = blockIdx.x;
    const int st = starts[b];
    const int len = ends[b] - st;         // 1..64

    qs[tid] = Q[(size_t)b * HID + tid];

    // bulk copy of contiguous K/V segment rows (coalesced float4 loads)
    const int nchunk = len * 64;          // float4 chunks per matrix
    for (int c = tid; c < nchunk; c += 256) {
        int r = c >> 6;
        int c4 = (c & 63) << 2;
        float4 kv = *(const float4*)&K[(size_t)(st + r) * HID + c4];
        float* d1 = &Ks[r * KS_STRIDE + c4];
        d1[0] = kv.x; d1[1] = kv.y; d1[2] = kv.z; d1[3] = kv.w;
        float4 vv = *(const float4*)&V[(size_t)(st + r) * HID + c4];
        float* d2 = &Vs[r * KS_STRIDE + c4];
        d2[0] = vv.x; d2[1] = vv.y; d2[2] = vv.z; d2[3] = vv.w;
    }
    __syncthreads();

    // scores: thread (head, m)
    {
        const int head = tid >> 6, m = tid & 63;
        float s = -1e30f;
        if (m < len) {
            const float* kr = &Ks[m * KS_STRIDE + head * 64];
            const float* qr = &qs[head * 64];
            s = 0.0f;
#pragma unroll
            for (int d = 0; d < 64; d++) s = fmaf(qr[d], kr[d], s);
        }
        sc[head * 64 + m] = s;
    }
    __syncthreads();

    // softmax: warp w -> head w (first 4 warps)
    if (tid < 128) {
        const int h = tid >> 5, l = tid & 31;
        float v0 = sc[h * 64 + l];
        float v1 = sc[h * 64 + 32 + l];
        float mx = fmaxf(v0, v1);
#pragma unroll
        for (int off = 16; off > 0; off >>= 1)
            mx = fmaxf(mx, __shfl_xor_sync(0xffffffffu, mx, off));
        float e0 = __expf(v0 - mx);
        float e1 = __expf(v1 - mx);
        float sum = e0 + e1;
#pragma unroll
        for (int off = 16; off > 0; off >>= 1)
            sum += __shfl_xor_sync(0xffffffffu, sum, off);
        float inv = 1.0f / sum;
        sc[h * 64 + l] = e0 * inv;
        sc[h * 64 + 32 + l] = e1 * inv;
    }
    __syncthreads();

    // out: thread = output channel j
    {
        const int head = tid >> 6, d = tid & 63;
        float o = 0.0f;
        const float* vp = &Vs[head * 64 + d];
        const float* ap = &sc[head * 64];
        for (int m = 0; m < len; m++)
            o = fmaf(ap[m], vp[m * KS_STRIDE], o);
        O[(size_t)b * HID + tid] = o;
    }
}

#define ATTN_SMEM ((2 * 64 * KS_STRIDE + 512) * (int)sizeof(float))

extern "C" void kernel_launch(void* const* d_in, const int* in_sizes, int n_in,
                              void* d_out, int out_size)
{
    const float* enc = (const float*)d_in[0];
    const float* soc = (const float*)d_in[1];
    const float* Wq = (const float*)d_in[2];
    const float* bq = (const float*)d_in[3];
    const float* Wk = (const float*)d_in[4];
    const float* bk = (const float*)d_in[5];
    const float* Wv = (const float*)d_in[6];
    const float* bv = (const float*)d_in[7];
    const float* Wf = (const float*)d_in[8];
    const float* bf = (const float*)d_in[9];
    const int* st = (const int*)d_in[10];
    const int* en = (const int*)d_in[11];
    float* out = (float*)d_out;

    float *qp, *kp, *vp, *op;
    cudaGetSymbolAddress((void**)&qp, g_Q);
    cudaGetSymbolAddress((void**)&kp, g_K);
    cudaGetSymbolAddress((void**)&vp, g_V);
    cudaGetSymbolAddress((void**)&op, g_O);

    cudaFuncSetAttribute(attn_kernel, cudaFuncAttributeMaxDynamicSharedMemorySize, ATTN_SMEM);

    dim3 blk(256);
    // Q = relu(enc @ Wq^T + bq) / 16
    gemm256<<<dim3(2, NB / 128), blk>>>(enc, Wq, bq, qp, 1, 0.0625f);
    // K, V over all rows
    gemm256<<<dim3(2, NTOT / 128), blk>>>(soc, Wk, bk, kp, 1, 1.0f);
    gemm256<<<dim3(2, NTOT / 128), blk>>>(soc, Wv, bv, vp, 1, 1.0f);
    // attention
    attn_kernel<<<NB, 256, ATTN_SMEM>>>(qp, kp, vp, st, en, op);
    // final projection (no relu)
    gemm256<<<dim3(2, NB / 128), blk>>>(op, Wf, bf, out, 0, 1.0f);
}

// round 4
// speedup vs baseline: 2.4513x; 2.4513x over previous
#include <cuda_runtime.h>
#include <cstdint>

#define HID 256
#define NB 4096
#define NTOT 131072

// Scratch (allocation-free rule: __device__ globals)
__device__ float g_Q[(size_t)NB * HID];
__device__ float g_K[(size_t)NTOT * HID];
__device__ float g_V[(size_t)NTOT * HID];
__device__ float g_O[(size_t)NB * HID];

// ======================= helpers =======================
__device__ __forceinline__ uint32_t tf32r(float x) {
    uint32_t r;
    asm("cvt.rna.tf32.f32 %0, %1;" : "=r"(r) : "f"(x));
    return r;
}
__device__ __forceinline__ void mma_tf32(float* d, const uint32_t* a, const uint32_t* b) {
    asm volatile(
        "mma.sync.aligned.m16n8k8.row.col.f32.tf32.tf32.f32 "
        "{%0,%1,%2,%3},{%4,%5,%6,%7},{%8,%9},{%0,%1,%2,%3};"
        : "+f"(d[0]), "+f"(d[1]), "+f"(d[2]), "+f"(d[3])
        : "r"(a[0]), "r"(a[1]), "r"(a[2]), "r"(a[3]), "r"(b[0]), "r"(b[1]));
}

// ======================= fused K+V projection (mma.sync tf32) =======================
// grid = NTOT/128, 256 threads (8 warps: 2m x 4n). A tile 128x256 resident in
// smem (tf32, stride 260). Weights streamed 128n x 32k chunks, register-prefetched.
// 4 passes: (Wk, n0..127), (Wk, n128..255), (Wv, n0..127), (Wv, n128..255).
#define AST 260
#define BST 36
#define KV_SMEM ((128 * AST + 128 * BST) * 4)

__global__ void __launch_bounds__(256, 1)
kv_mma(const float* __restrict__ soc,
       const float* __restrict__ Wk, const float* __restrict__ bk,
       const float* __restrict__ Wv, const float* __restrict__ bv,
       float* __restrict__ Kout, float* __restrict__ Vout)
{
    extern __shared__ uint32_t sm32[];
    uint32_t* As = sm32;                 // 128*260 words
    uint32_t* Bs = sm32 + 128 * AST;     // 128*36 words

    const int tid = threadIdx.x;
    const int lane = tid & 31;
    const int wid = tid >> 5;
    const int wm = wid & 1;              // m half (64 rows)
    const int wn = wid >> 1;             // n quarter (32 cols)
    const int bm = blockIdx.x;

    // ---- stage A tile 128x256 (tf32-rounded) ----
    const float* Ab = soc + (size_t)bm * 128 * HID;
#pragma unroll
    for (int i = 0; i < 32; i++) {
        int idx = i * 256 + tid;
        int r = idx >> 6, c4 = (idx & 63) << 2;
        float4 v = *(const float4*)(Ab + (size_t)r * HID + c4);
        *(uint4*)&As[r * AST + c4] =
            make_uint4(tf32r(v.x), tf32r(v.y), tf32r(v.z), tf32r(v.w));
    }

    // ---- prefetch B chunk 0 ----
    float4 pf[4];
    {
        const int k = (tid & 7) * 4;
        const int nb = tid >> 3;
#pragma unroll
        for (int q = 0; q < 4; q++)
            pf[q] = *(const float4*)&Wk[(size_t)(nb + q * 32) * HID + k];
    }
    __syncthreads();

    float acc[4][4][4];
#pragma unroll
    for (int i = 0; i < 4; i++)
#pragma unroll
        for (int j = 0; j < 4; j++)
#pragma unroll
            for (int t = 0; t < 4; t++) acc[i][j][t] = 0.0f;

    for (int tc = 0; tc < 32; tc++) {
        const int p = tc >> 3;           // pass 0..3
        const int kc = tc & 7;           // k chunk 0..7

        // store prefetched chunk into Bs (tf32-rounded)
        {
            const int nloc0 = tid >> 3;
            const int k4 = (tid & 7) * 4;
#pragma unroll
            for (int q = 0; q < 4; q++)
                *(uint4*)&Bs[(nloc0 + q * 32) * BST + k4] =
                    make_uint4(tf32r(pf[q].x), tf32r(pf[q].y), tf32r(pf[q].z), tf32r(pf[q].w));
        }
        __syncthreads();

        // prefetch next chunk
        if (tc < 31) {
            const int ntc = tc + 1;
            const int np = ntc >> 3, nkc = ntc & 7;
            const float* W = (np < 2) ? Wk : Wv;
            const int nh = np & 1;
            const int k = nkc * 32 + (tid & 7) * 4;
            const int nb = nh * 128 + (tid >> 3);
#pragma unroll
            for (int q = 0; q < 4; q++)
                pf[q] = *(const float4*)&W[(size_t)(nb + q * 32) * HID + k];
        }

        // mma over 4 k8 steps
        const int k0 = kc * 32;
#pragma unroll
        for (int ks = 0; ks < 4; ks++) {
            const int c = k0 + ks * 8 + (lane & 3);
            uint32_t a[4][4];
#pragma unroll
            for (int i = 0; i < 4; i++) {
                const int r = wm * 64 + i * 16 + (lane >> 2);
                a[i][0] = As[r * AST + c];
                a[i][1] = As[(r + 8) * AST + c];
                a[i][2] = As[r * AST + c + 4];
                a[i][3] = As[(r + 8) * AST + c + 4];
            }
            uint32_t b[4][2];
            const int kk = ks * 8 + (lane & 3);
#pragma unroll
            for (int j = 0; j < 4; j++) {
                const int n = wn * 32 + j * 8 + (lane >> 2);
                b[j][0] = Bs[n * BST + kk];
                b[j][1] = Bs[n * BST + kk + 4];
            }
#pragma unroll
            for (int i = 0; i < 4; i++)
#pragma unroll
                for (int j = 0; j < 4; j++) mma_tf32(acc[i][j], a[i], b[j]);
        }
        __syncthreads();

        // end of a pass -> epilogue + reset accum
        if (kc == 7) {
            const float* bias = (p < 2) ? bk : bv;
            float* Cout = (p < 2) ? Kout : Vout;
            const int nh = p & 1;
            const int colw = nh * 128 + wn * 32 + (lane & 3) * 2;
            const size_t rowb = (size_t)bm * 128 + wm * 64 + (lane >> 2);
#pragma unroll
            for (int j = 0; j < 4; j++) {
                const float2 bb = *(const float2*)&bias[colw + j * 8];
#pragma unroll
                for (int i = 0; i < 4; i++) {
                    const size_t r0 = rowb + i * 16;
                    float2 o0, o1;
                    o0.x = fmaxf(acc[i][j][0] + bb.x, 0.0f);
                    o0.y = fmaxf(acc[i][j][1] + bb.y, 0.0f);
                    o1.x = fmaxf(acc[i][j][2] + bb.x, 0.0f);
                    o1.y = fmaxf(acc[i][j][3] + bb.y, 0.0f);
                    *(float2*)&Cout[r0 * HID + colw + j * 8] = o0;
                    *(float2*)&Cout[(r0 + 8) * HID + colw + j * 8] = o1;
#pragma unroll
                    for (int t = 0; t < 4; t++) acc[i][j][t] = 0.0f;
                }
            }
        }
    }
}

// ======================= fp32 FFMA GEMM (Q, final) =======================
__device__ __forceinline__ unsigned long long pk2(float x, float y) {
    unsigned long long r;
    asm("mov.b64 %0,{%1,%2};" : "=l"(r) : "f"(x), "f"(y));
    return r;
}
__device__ __forceinline__ void upk2(unsigned long long v, float& x, float& y) {
    asm("mov.b64 {%0,%1},%2;" : "=f"(x), "=f"(y) : "l"(v));
}
__device__ __forceinline__ void ffma2(unsigned long long& d, unsigned long long a, unsigned long long b) {
    asm("fma.rn.f32x2 %0,%1,%2,%0;" : "+l"(d) : "l"(a), "l"(b));
}

__global__ __launch_bounds__(256, 2) void gemm256(
    const float* __restrict__ A, const float* __restrict__ W,
    const float* __restrict__ bias, float* __restrict__ C,
    int doRelu, float scale)
{
    __shared__ float As[16][128];
    __shared__ float Bs[16][128];

    const int tid = threadIdx.x;
    const int bm = blockIdx.y, bn = blockIdx.x;
    const int tx = tid & 15, ty = tid >> 4;
    const int r0 = tid >> 2, c0 = (tid & 3) << 2;

    const float* Ag = A + (size_t)(bm * 128 + r0) * HID + c0;
    const float* Wg = W + (size_t)(bn * 128 + r0) * HID + c0;

    unsigned long long acc[8][4];
#pragma unroll
    for (int i = 0; i < 8; i++)
#pragma unroll
        for (int j = 0; j < 4; j++) acc[i][j] = 0ull;

    for (int kt = 0; kt < 16; kt++) {
        const int k0 = kt * 16;
#pragma unroll
        for (int p = 0; p < 2; p++) {
            float4 av = *(const float4*)(Ag + (size_t)p * 64 * HID + k0);
            float4 wv = *(const float4*)(Wg + (size_t)p * 64 * HID + k0);
            As[c0 + 0][r0 + p * 64] = av.x;
            As[c0 + 1][r0 + p * 64] = av.y;
            As[c0 + 2][r0 + p * 64] = av.z;
            As[c0 + 3][r0 + p * 64] = av.w;
            Bs[c0 + 0][r0 + p * 64] = wv.x;
            Bs[c0 + 1][r0 + p * 64] = wv.y;
            Bs[c0 + 2][r0 + p * 64] = wv.z;
            Bs[c0 + 3][r0 + p * 64] = wv.w;
        }
        __syncthreads();
#pragma unroll
        for (int kk = 0; kk < 16; kk++) {
            float a[8];
            *(float4*)&a[0] = *(const float4*)&As[kk][ty * 8];
            *(float4*)&a[4] = *(const float4*)&As[kk][ty * 8 + 4];
            unsigned long long bb[4];
#pragma unroll
            for (int j = 0; j < 4; j++)
                bb[j] = *(const unsigned long long*)&Bs[kk][tx * 8 + 2 * j];
#pragma unroll
            for (int i = 0; i < 8; i++) {
                unsigned long long aa = pk2(a[i], a[i]);
#pragma unroll
                for (int j = 0; j < 4; j++) ffma2(acc[i][j], aa, bb[j]);
            }
        }
        __syncthreads();
    }

    const int col = bn * 128 + tx * 8;
    float bvv[8];
#pragma unroll
    for (int j = 0; j < 8; j++) bvv[j] = bias[col + j];

#pragma unroll
    for (int i = 0; i < 8; i++) {
        float out[8];
#pragma unroll
        for (int j = 0; j < 4; j++) {
            float x, y;
            upk2(acc[i][j], x, y);
            out[2 * j] = x + bvv[2 * j];
            out[2 * j + 1] = y + bvv[2 * j + 1];
        }
        if (doRelu) {
#pragma unroll
            for (int j = 0; j < 8; j++) out[j] = fmaxf(out[j], 0.0f);
        }
#pragma unroll
        for (int j = 0; j < 8; j++) out[j] *= scale;
        const int rowi = bm * 128 + ty * 8 + i;
        *(float4*)&C[(size_t)rowi * HID + col] = make_float4(out[0], out[1], out[2], out[3]);
        *(float4*)&C[(size_t)rowi * HID + col + 4] = make_float4(out[4], out[5], out[6], out[7]);
    }
}

// ======================= attention: 1 CTA / sample, no K staging =======================
// Scores: warp w processes rows m = w, w+8, ..; lanes load 8 consecutive K floats
// (coalesced), FMA vs register q, 8-lane segmented shuffle reduce -> score per head.
// AV: thread = output channel, V streamed coalesced from gmem. smem = 2KB.
__global__ __launch_bounds__(256) void attn3(
    const float* __restrict__ Q, const float* __restrict__ K,
    const float* __restrict__ V, const int* __restrict__ starts,
    const int* __restrict__ ends, float* __restrict__ O)
{
    __shared__ float qs[256];
    __shared__ float sc[256];

    const int tid = threadIdx.x;
    const int lane = tid & 31;
    const int wid = tid >> 5;
    const int b = blockIdx.x;
    const int st = starts[b];
    const int len = ends[b] - st;     // 1..64

    qs[tid] = Q[(size_t)b * HID + tid];
    sc[tid] = -1e30f;
    __syncthreads();

    // register-resident q slice for this lane (8 floats at lane*8)
    float4 q0 = *(const float4*)&qs[lane * 8];
    float4 q1 = *(const float4*)&qs[lane * 8 + 4];
    const int head = lane >> 3;       // 8*lane .. 8*lane+7 lies in head lane>>3

    // scores
#pragma unroll
    for (int rr = 0; rr < 8; rr++) {
        const int m = rr * 8 + wid;
        if (m < len) {
            const float* kr = K + (size_t)(st + m) * HID + lane * 8;
            float4 k0 = *(const float4*)kr;
            float4 k1 = *(const float4*)(kr + 4);
            float p = q0.x * k0.x + q0.y * k0.y + q0.z * k0.z + q0.w * k0.w
                    + q1.x * k1.x + q1.y * k1.y + q1.z * k1.z + q1.w * k1.w;
            p += __shfl_down_sync(0xffffffffu, p, 4);
            p += __shfl_down_sync(0xffffffffu, p, 2);
            p += __shfl_down_sync(0xffffffffu, p, 1);
            if ((lane & 7) == 0) sc[head * 64 + m] = p;
        }
    }
    __syncthreads();

    // softmax: warp w -> head w (first 4 warps)
    if (tid < 128) {
        const int h = tid >> 5, l = tid & 31;
        float v0 = sc[h * 64 + l];
        float v1 = sc[h * 64 + 32 + l];
        float mx = fmaxf(v0, v1);
#pragma unroll
        for (int off = 16; off > 0; off >>= 1)
            mx = fmaxf(mx, __shfl_xor_sync(0xffffffffu, mx, off));
        float e0 = __expf(v0 - mx);
        float e1 = __expf(v1 - mx);
        float sum = e0 + e1;
#pragma unroll
        for (int off = 16; off > 0; off >>= 1)
            sum += __shfl_xor_sync(0xffffffffu, sum, off);
        float inv = 1.0f / sum;
        sc[h * 64 + l] = e0 * inv;
        sc[h * 64 + 32 + l] = e1 * inv;
    }
    __syncthreads();

    // out: thread = output channel (col = tid), V streamed from gmem coalesced
    {
        const int h = tid >> 6;
        const float* vp = V + (size_t)st * HID + tid;
        const float* ap = &sc[h * 64];
        float o = 0.0f;
        int m = 0;
        for (; m + 4 <= len; m += 4) {
            float a0 = ap[m], a1 = ap[m + 1], a2 = ap[m + 2], a3 = ap[m + 3];
            float v0 = vp[(size_t)m * HID];
            float v1 = vp[(size_t)(m + 1) * HID];
            float v2 = vp[(size_t)(m + 2) * HID];
            float v3 = vp[(size_t)(m + 3) * HID];
            o = fmaf(a0, v0, o); o = fmaf(a1, v1, o);
            o = fmaf(a2, v2, o); o = fmaf(a3, v3, o);
        }
        for (; m < len; m++) o = fmaf(ap[m], vp[(size_t)m * HID], o);
        O[(size_t)b * HID + tid] = o;
    }
}

// ======================= launch =======================
extern "C" void kernel_launch(void* const* d_in, const int* in_sizes, int n_in,
                              void* d_out, int out_size)
{
    const float* enc = (const float*)d_in[0];
    const float* soc = (const float*)d_in[1];
    const float* Wq = (const float*)d_in[2];
    const float* bq = (const float*)d_in[3];
    const float* Wk = (const float*)d_in[4];
    const float* bk = (const float*)d_in[5];
    const float* Wv = (const float*)d_in[6];
    const float* bv = (const float*)d_in[7];
    const float* Wf = (const float*)d_in[8];
    const float* bf = (const float*)d_in[9];
    const int* st = (const int*)d_in[10];
    const int* en = (const int*)d_in[11];
    float* out = (float*)d_out;

    float *qp, *kp, *vp, *op;
    cudaGetSymbolAddress((void**)&qp, g_Q);
    cudaGetSymbolAddress((void**)&kp, g_K);
    cudaGetSymbolAddress((void**)&vp, g_V);
    cudaGetSymbolAddress((void**)&op, g_O);

    cudaFuncSetAttribute(kv_mma, cudaFuncAttributeMaxDynamicSharedMemorySize, KV_SMEM);

    dim3 blk(256);
    // Q = relu(enc @ Wq^T + bq) / 16
    gemm256<<<dim3(2, NB / 128), blk>>>(enc, Wq, bq, qp, 1, 0.0625f);
    // fused K,V = relu(soc @ W^T + b) via mma.sync tf32
    kv_mma<<<NTOT / 128, 256, KV_SMEM>>>(soc, Wk, bk, Wv, bv, kp, vp);
    // attention
    attn3<<<NB, 256>>>(qp, kp, vp, st, en, op);
    // final projection (no relu)
    gemm256<<<dim3(2, NB / 128), blk>>>(op, Wf, bf, out, 0, 1.0f);
}

// round 5
// speedup vs baseline: 3.3876x; 1.3820x over previous
#include <cuda_runtime.h>
#include <cuda_fp16.h>
#include <cstdint>

#define HID 256
#define NB 4096
#define NTOT 131072

// Scratch (allocation-free rule: __device__ globals)
__device__ float g_Q[(size_t)NB * HID];
__device__ float g_K[(size_t)NTOT * HID];
__device__ float g_V[(size_t)NTOT * HID];
__device__ float g_O[(size_t)NB * HID];

// ======================= fp16 mma helper =======================
__device__ __forceinline__ void mma_f16(float* d, const uint32_t* a, const uint32_t* b) {
    asm volatile(
        "mma.sync.aligned.m16n8k16.row.col.f32.f16.f16.f32 "
        "{%0,%1,%2,%3},{%4,%5,%6,%7},{%8,%9},{%0,%1,%2,%3};"
        : "+f"(d[0]), "+f"(d[1]), "+f"(d[2]), "+f"(d[3])
        : "r"(a[0]), "r"(a[1]), "r"(a[2]), "r"(a[3]), "r"(b[0]), "r"(b[1]));
}
__device__ __forceinline__ uint32_t h2u(float lo, float hi) {
    __half2 h = __floats2half2_rn(lo, hi);
    return *(uint32_t*)&h;
}

// ======================= fused K+V projection (mma.sync fp16, f32 accum) ==========
// grid = NTOT/128, 256 threads (8 warps: 2m x 4n). A tile 128x256 resident in smem
// as half2 (stride 132 half2 -> conflict-free frags). Weights streamed 128n x 32k
// chunks (half2, stride 20), register-prefetched. 4 passes:
// (Wk, n0..127), (Wk, n128..255), (Wv, n0..127), (Wv, n128..255).
#define AST2 132
#define BST2 20
#define KV_SMEM ((128 * AST2 + 128 * BST2) * 4)

__global__ void __launch_bounds__(256, 1)
kv_mma(const float* __restrict__ soc,
       const float* __restrict__ Wk, const float* __restrict__ bk,
       const float* __restrict__ Wv, const float* __restrict__ bv,
       float* __restrict__ Kout, float* __restrict__ Vout)
{
    extern __shared__ uint32_t sm32[];
    uint32_t* As = sm32;                 // 128 * 132 half2 words
    uint32_t* Bs = sm32 + 128 * AST2;    // 128 * 20 half2 words

    const int tid = threadIdx.x;
    const int lane = tid & 31;
    const int wid = tid >> 5;
    const int wm = wid & 1;              // m half (64 rows)
    const int wn = wid >> 1;             // n quarter (32 cols)
    const int bm = blockIdx.x;

    // ---- stage A tile 128x256 -> fp16 ----
    const float* Ab = soc + (size_t)bm * 128 * HID;
#pragma unroll
    for (int i = 0; i < 32; i++) {
        int idx = i * 256 + tid;
        int r = idx >> 6, c4 = (idx & 63) << 2;
        float4 v = *(const float4*)(Ab + (size_t)r * HID + c4);
        uint2 h;
        h.x = h2u(v.x, v.y);
        h.y = h2u(v.z, v.w);
        *(uint2*)&As[r * AST2 + (c4 >> 1)] = h;
    }

    // ---- prefetch B chunk 0 (Wk, kc=0) ----
    float4 pf[4];
    {
        const int k = (tid & 7) * 4;
        const int nb = tid >> 3;
#pragma unroll
        for (int q = 0; q < 4; q++)
            pf[q] = *(const float4*)&Wk[(size_t)(nb + q * 32) * HID + k];
    }
    __syncthreads();

    float acc[4][4][4];
#pragma unroll
    for (int i = 0; i < 4; i++)
#pragma unroll
        for (int j = 0; j < 4; j++)
#pragma unroll
            for (int t = 0; t < 4; t++) acc[i][j][t] = 0.0f;

    for (int tc = 0; tc < 32; tc++) {
        const int p = tc >> 3;           // pass 0..3
        const int kc = tc & 7;           // k chunk 0..7 (32 k each)

        // store prefetched chunk into Bs (fp16)
        {
            const int nloc0 = tid >> 3;
            const int c2 = (tid & 7) * 2;  // half2 offset within 16
#pragma unroll
            for (int q = 0; q < 4; q++) {
                uint2 h;
                h.x = h2u(pf[q].x, pf[q].y);
                h.y = h2u(pf[q].z, pf[q].w);
                *(uint2*)&Bs[(nloc0 + q * 32) * BST2 + c2] = h;
            }
        }
        __syncthreads();

        // prefetch next chunk
        if (tc < 31) {
            const int ntc = tc + 1;
            const int np = ntc >> 3, nkc = ntc & 7;
            const float* W = (np < 2) ? Wk : Wv;
            const int nh = np & 1;
            const int k = nkc * 32 + (tid & 7) * 4;
            const int nb = nh * 128 + (tid >> 3);
#pragma unroll
            for (int q = 0; q < 4; q++)
                pf[q] = *(const float4*)&W[(size_t)(nb + q * 32) * HID + k];
        }

        // mma: 2 k16 steps per 32-k chunk
#pragma unroll
        for (int ks = 0; ks < 2; ks++) {
            const int kb = kc * 16 + ks * 8;   // half2 base in As
            uint32_t a[4][4];
#pragma unroll
            for (int i = 0; i < 4; i++) {
                const int r = wm * 64 + i * 16 + (lane >> 2);
                const int c = kb + (lane & 3);
                a[i][0] = As[r * AST2 + c];
                a[i][1] = As[(r + 8) * AST2 + c];
                a[i][2] = As[r * AST2 + c + 4];
                a[i][3] = As[(r + 8) * AST2 + c + 4];
            }
            uint32_t b[4][2];
            const int ck = ks * 8 + (lane & 3);
#pragma unroll
            for (int j = 0; j < 4; j++) {
                const int n = wn * 32 + j * 8 + (lane >> 2);
                b[j][0] = Bs[n * BST2 + ck];
                b[j][1] = Bs[n * BST2 + ck + 4];
            }
#pragma unroll
            for (int i = 0; i < 4; i++)
#pragma unroll
                for (int j = 0; j < 4; j++) mma_f16(acc[i][j], a[i], b[j]);
        }
        __syncthreads();

        // end of a pass -> epilogue + reset accum
        if (kc == 7) {
            const float* bias = (p < 2) ? bk : bv;
            float* Cout = (p < 2) ? Kout : Vout;
            const int nh = p & 1;
            const int colw = nh * 128 + wn * 32 + (lane & 3) * 2;
            const size_t rowb = (size_t)bm * 128 + wm * 64 + (lane >> 2);
#pragma unroll
            for (int j = 0; j < 4; j++) {
                const float2 bb = *(const float2*)&bias[colw + j * 8];
#pragma unroll
                for (int i = 0; i < 4; i++) {
                    const size_t r0 = rowb + i * 16;
                    float2 o0, o1;
                    o0.x = fmaxf(acc[i][j][0] + bb.x, 0.0f);
                    o0.y = fmaxf(acc[i][j][1] + bb.y, 0.0f);
                    o1.x = fmaxf(acc[i][j][2] + bb.x, 0.0f);
                    o1.y = fmaxf(acc[i][j][3] + bb.y, 0.0f);
                    *(float2*)&Cout[r0 * HID + colw + j * 8] = o0;
                    *(float2*)&Cout[(r0 + 8) * HID + colw + j * 8] = o1;
#pragma unroll
                    for (int t = 0; t < 4; t++) acc[i][j][t] = 0.0f;
                }
            }
        }
    }
}

// ======================= fp32 FFMA GEMM, 64x128 tiles (Q, final) =======================
__device__ __forceinline__ unsigned long long pk2(float x, float y) {
    unsigned long long r;
    asm("mov.b64 %0,{%1,%2};" : "=l"(r) : "f"(x), "f"(y));
    return r;
}
__device__ __forceinline__ void upk2(unsigned long long v, float& x, float& y) {
    asm("mov.b64 {%0,%1},%2;" : "=f"(x), "=f"(y) : "l"(v));
}
__device__ __forceinline__ void ffma2(unsigned long long& d, unsigned long long a, unsigned long long b) {
    asm("fma.rn.f32x2 %0,%1,%2,%0;" : "+l"(d) : "l"(a), "l"(b));
}

__global__ __launch_bounds__(256, 3) void gemm64(
    const float* __restrict__ A, const float* __restrict__ W,
    const float* __restrict__ bias, float* __restrict__ C,
    int doRelu, float scale)
{
    __shared__ float As[16][64];
    __shared__ float Bs[16][128];

    const int tid = threadIdx.x;
    const int bm = blockIdx.y, bn = blockIdx.x;
    const int tx = tid & 15, ty = tid >> 4;
    const int r0 = tid >> 2, c0 = (tid & 3) << 2;

    const float* Ag = A + (size_t)(bm * 64 + r0) * HID + c0;
    const float* Wg = W + (size_t)(bn * 128 + r0) * HID + c0;

    unsigned long long acc[4][4];
#pragma unroll
    for (int i = 0; i < 4; i++)
#pragma unroll
        for (int j = 0; j < 4; j++) acc[i][j] = 0ull;

    for (int kt = 0; kt < 16; kt++) {
        const int k0 = kt * 16;
        {
            float4 av = *(const float4*)(Ag + k0);
            As[c0 + 0][r0] = av.x;
            As[c0 + 1][r0] = av.y;
            As[c0 + 2][r0] = av.z;
            As[c0 + 3][r0] = av.w;
#pragma unroll
            for (int p = 0; p < 2; p++) {
                float4 wv = *(const float4*)(Wg + (size_t)p * 64 * HID + k0);
                Bs[c0 + 0][r0 + p * 64] = wv.x;
                Bs[c0 + 1][r0 + p * 64] = wv.y;
                Bs[c0 + 2][r0 + p * 64] = wv.z;
                Bs[c0 + 3][r0 + p * 64] = wv.w;
            }
        }
        __syncthreads();
#pragma unroll
        for (int kk = 0; kk < 16; kk++) {
            float a[4];
            *(float4*)&a[0] = *(const float4*)&As[kk][ty * 4];
            unsigned long long bb[4];
#pragma unroll
            for (int j = 0; j < 4; j++)
                bb[j] = *(const unsigned long long*)&Bs[kk][tx * 8 + 2 * j];
#pragma unroll
            for (int i = 0; i < 4; i++) {
                unsigned long long aa = pk2(a[i], a[i]);
#pragma unroll
                for (int j = 0; j < 4; j++) ffma2(acc[i][j], aa, bb[j]);
            }
        }
        __syncthreads();
    }

    const int col = bn * 128 + tx * 8;
    float bvv[8];
#pragma unroll
    for (int j = 0; j < 8; j++) bvv[j] = bias[col + j];

#pragma unroll
    for (int i = 0; i < 4; i++) {
        float out[8];
#pragma unroll
        for (int j = 0; j < 4; j++) {
            float x, y;
            upk2(acc[i][j], x, y);
            out[2 * j] = x + bvv[2 * j];
            out[2 * j + 1] = y + bvv[2 * j + 1];
        }
        if (doRelu) {
#pragma unroll
            for (int j = 0; j < 8; j++) out[j] = fmaxf(out[j], 0.0f);
        }
#pragma unroll
        for (int j = 0; j < 8; j++) out[j] *= scale;
        const int rowi = bm * 64 + ty * 4 + i;
        *(float4*)&C[(size_t)rowi * HID + col] = make_float4(out[0], out[1], out[2], out[3]);
        *(float4*)&C[(size_t)rowi * HID + col + 4] = make_float4(out[4], out[5], out[6], out[7]);
    }
}

// ======================= attention: 1 CTA / sample, no K staging =======================
__global__ __launch_bounds__(256) void attn3(
    const float* __restrict__ Q, const float* __restrict__ K,
    const float* __restrict__ V, const int* __restrict__ starts,
    const int* __restrict__ ends, float* __restrict__ O)
{
    __shared__ float qs[256];
    __shared__ float sc[256];

    const int tid = threadIdx.x;
    const int lane = tid & 31;
    const int wid = tid >> 5;
    const int b = blockIdx.x;
    const int st = starts[b];
    const int len = ends[b] - st;     // 1..64

    qs[tid] = Q[(size_t)b * HID + tid];
    sc[tid] = -1e30f;
    __syncthreads();

    float4 q0 = *(const float4*)&qs[lane * 8];
    float4 q1 = *(const float4*)&qs[lane * 8 + 4];
    const int head = lane >> 3;

    // scores
#pragma unroll
    for (int rr = 0; rr < 8; rr++) {
        const int m = rr * 8 + wid;
        if (m < len) {
            const float* kr = K + (size_t)(st + m) * HID + lane * 8;
            float4 k0 = *(const float4*)kr;
            float4 k1 = *(const float4*)(kr + 4);
            float p = q0.x * k0.x + q0.y * k0.y + q0.z * k0.z + q0.w * k0.w
                    + q1.x * k1.x + q1.y * k1.y + q1.z * k1.z + q1.w * k1.w;
            p += __shfl_down_sync(0xffffffffu, p, 4);
            p += __shfl_down_sync(0xffffffffu, p, 2);
            p += __shfl_down_sync(0xffffffffu, p, 1);
            if ((lane & 7) == 0) sc[head * 64 + m] = p;
        }
    }
    __syncthreads();

    // softmax: warp w -> head w (first 4 warps)
    if (tid < 128) {
        const int h = tid >> 5, l = tid & 31;
        float v0 = sc[h * 64 + l];
        float v1 = sc[h * 64 + 32 + l];
        float mx = fmaxf(v0, v1);
#pragma unroll
        for (int off = 16; off > 0; off >>= 1)
            mx = fmaxf(mx, __shfl_xor_sync(0xffffffffu, mx, off));
        float e0 = __expf(v0 - mx);
        float e1 = __expf(v1 - mx);
        float sum = e0 + e1;
#pragma unroll
        for (int off = 16; off > 0; off >>= 1)
            sum += __shfl_xor_sync(0xffffffffu, sum, off);
        float inv = 1.0f / sum;
        sc[h * 64 + l] = e0 * inv;
        sc[h * 64 + 32 + l] = e1 * inv;
    }
    __syncthreads();

    // out: thread = output channel, V streamed from gmem coalesced
    {
        const int h = tid >> 6;
        const float* vp = V + (size_t)st * HID + tid;
        const float* ap = &sc[h * 64];
        float o = 0.0f;
        int m = 0;
        for (; m + 4 <= len; m += 4) {
            float a0 = ap[m], a1 = ap[m + 1], a2 = ap[m + 2], a3 = ap[m + 3];
            float v0 = vp[(size_t)m * HID];
            float v1 = vp[(size_t)(m + 1) * HID];
            float v2 = vp[(size_t)(m + 2) * HID];
            float v3 = vp[(size_t)(m + 3) * HID];
            o = fmaf(a0, v0, o); o = fmaf(a1, v1, o);
            o = fmaf(a2, v2, o); o = fmaf(a3, v3, o);
        }
        for (; m < len; m++) o = fmaf(ap[m], vp[(size_t)m * HID], o);
        O[(size_t)b * HID + tid] = o;
    }
}

// ======================= launch =======================
extern "C" void kernel_launch(void* const* d_in, const int* in_sizes, int n_in,
                              void* d_out, int out_size)
{
    const float* enc = (const float*)d_in[0];
    const float* soc = (const float*)d_in[1];
    const float* Wq = (const float*)d_in[2];
    const float* bq = (const float*)d_in[3];
    const float* Wk = (const float*)d_in[4];
    const float* bk = (const float*)d_in[5];
    const float* Wv = (const float*)d_in[6];
    const float* bv = (const float*)d_in[7];
    const float* Wf = (const float*)d_in[8];
    const float* bf = (const float*)d_in[9];
    const int* st = (const int*)d_in[10];
    const int* en = (const int*)d_in[11];
    float* out = (float*)d_out;

    float *qp, *kp, *vp, *op;
    cudaGetSymbolAddress((void**)&qp, g_Q);
    cudaGetSymbolAddress((void**)&kp, g_K);
    cudaGetSymbolAddress((void**)&vp, g_V);
    cudaGetSymbolAddress((void**)&op, g_O);

    cudaFuncSetAttribute(kv_mma, cudaFuncAttributeMaxDynamicSharedMemorySize, KV_SMEM);

    // Q = relu(enc @ Wq^T + bq) / 16
    gemm64<<<dim3(2, NB / 64), 256>>>(enc, Wq, bq, qp, 1, 0.0625f);
    // fused K,V = relu(soc @ W^T + b) via mma.sync fp16 (f32 accum)
    kv_mma<<<NTOT / 128, 256, KV_SMEM>>>(soc, Wk, bk, Wv, bv, kp, vp);
    // attention
    attn3<<<NB, 256>>>(qp, kp, vp, st, en, op);
    // final projection (no relu)
    gemm64<<<dim3(2, NB / 64), 256>>>(op, Wf, bf, out, 0, 1.0f);
}

// round 6
// speedup vs baseline: 3.9914x; 1.1782x over previous
#include <cuda_runtime.h>
#include <cuda_fp16.h>
#include <cstdint>

#define HID 256
#define NB 4096
#define NTOT 131072

// Scratch (allocation-free rule: __device__ globals)
__device__ float  g_Q[(size_t)NB * HID];
__device__ __half g_K[(size_t)NTOT * HID];
__device__ __half g_V[(size_t)NTOT * HID];
__device__ float  g_O[(size_t)NB * HID];

// ======================= fp16 mma helper =======================
__device__ __forceinline__ void mma_f16(float* d, const uint32_t* a, const uint32_t* b) {
    asm volatile(
        "mma.sync.aligned.m16n8k16.row.col.f32.f16.f16.f32 "
        "{%0,%1,%2,%3},{%4,%5,%6,%7},{%8,%9},{%0,%1,%2,%3};"
        : "+f"(d[0]), "+f"(d[1]), "+f"(d[2]), "+f"(d[3])
        : "r"(a[0]), "r"(a[1]), "r"(a[2]), "r"(a[3]), "r"(b[0]), "r"(b[1]));
}
__device__ __forceinline__ uint32_t h2u(float lo, float hi) {
    __half2 h = __floats2half2_rn(lo, hi);
    return *(uint32_t*)&h;
}

// ======================= fused K+V projection (mma.sync fp16, f32 accum) ==========
// grid = NTOT/128, 256 threads (8 warps: 2m x 4n). A tile 128x256 resident in smem
// as half2 (stride 132). Weights streamed 128n x 32k chunks into DOUBLE-buffered Bs
// (stride 20), register-prefetched; ONE __syncthreads per chunk. Outputs fp16.
#define AST2 132
#define BST2 20
#define KV_SMEM ((128 * AST2 + 2 * 128 * BST2) * 4)

__global__ void __launch_bounds__(256, 2)
kv_mma(const float* __restrict__ soc,
       const float* __restrict__ Wk, const float* __restrict__ bk,
       const float* __restrict__ Wv, const float* __restrict__ bv,
       __half* __restrict__ Kout, __half* __restrict__ Vout)
{
    extern __shared__ uint32_t sm32[];
    uint32_t* As = sm32;                  // 128 * 132 half2 words
    uint32_t* Bs = sm32 + 128 * AST2;     // 2 buffers of 128 * 20 half2 words

    const int tid = threadIdx.x;
    const int lane = tid & 31;
    const int wid = tid >> 5;
    const int wm = wid & 1;               // m half (64 rows)
    const int wn = wid >> 1;              // n quarter (32 cols)
    const int bm = blockIdx.x;

    // ---- stage A tile 128x256 -> fp16 ----
    const float* Ab = soc + (size_t)bm * 128 * HID;
#pragma unroll
    for (int i = 0; i < 32; i++) {
        int idx = i * 256 + tid;
        int r = idx >> 6, c4 = (idx & 63) << 2;
        float4 v = *(const float4*)(Ab + (size_t)r * HID + c4);
        uint2 h;
        h.x = h2u(v.x, v.y);
        h.y = h2u(v.z, v.w);
        *(uint2*)&As[r * AST2 + (c4 >> 1)] = h;
    }

    // ---- prefetch B chunk 0 (Wk, kc=0) ----
    float4 pf[4];
    {
        const int k = (tid & 7) * 4;
        const int nb = tid >> 3;
#pragma unroll
        for (int q = 0; q < 4; q++)
            pf[q] = *(const float4*)&Wk[(size_t)(nb + q * 32) * HID + k];
    }

    float acc[4][4][4];
#pragma unroll
    for (int i = 0; i < 4; i++)
#pragma unroll
        for (int j = 0; j < 4; j++)
#pragma unroll
            for (int t = 0; t < 4; t++) acc[i][j][t] = 0.0f;

    for (int tc = 0; tc < 32; tc++) {
        const int p = tc >> 3;            // pass 0..3
        const int kc = tc & 7;            // k chunk 0..7 (32 k each)
        uint32_t* Bb = Bs + (tc & 1) * (128 * BST2);

        // store prefetched chunk into Bb (fp16)
        {
            const int nloc0 = tid >> 3;
            const int c2 = (tid & 7) * 2;
#pragma unroll
            for (int q = 0; q < 4; q++) {
                uint2 h;
                h.x = h2u(pf[q].x, pf[q].y);
                h.y = h2u(pf[q].z, pf[q].w);
                *(uint2*)&Bb[(nloc0 + q * 32) * BST2 + c2] = h;
            }
        }
        __syncthreads();

        // prefetch next chunk
        if (tc < 31) {
            const int ntc = tc + 1;
            const int np = ntc >> 3, nkc = ntc & 7;
            const float* W = (np < 2) ? Wk : Wv;
            const int nh = np & 1;
            const int k = nkc * 32 + (tid & 7) * 4;
            const int nb = nh * 128 + (tid >> 3);
#pragma unroll
            for (int q = 0; q < 4; q++)
                pf[q] = *(const float4*)&W[(size_t)(nb + q * 32) * HID + k];
        }

        // mma: 2 k16 steps per 32-k chunk
#pragma unroll
        for (int ks = 0; ks < 2; ks++) {
            const int kb = kc * 16 + ks * 8;   // half2 base in As
            uint32_t a[4][4];
#pragma unroll
            for (int i = 0; i < 4; i++) {
                const int r = wm * 64 + i * 16 + (lane >> 2);
                const int c = kb + (lane & 3);
                a[i][0] = As[r * AST2 + c];
                a[i][1] = As[(r + 8) * AST2 + c];
                a[i][2] = As[r * AST2 + c + 4];
                a[i][3] = As[(r + 8) * AST2 + c + 4];
            }
            uint32_t b[4][2];
            const int ck = ks * 8 + (lane & 3);
#pragma unroll
            for (int j = 0; j < 4; j++) {
                const int n = wn * 32 + j * 8 + (lane >> 2);
                b[j][0] = Bb[n * BST2 + ck];
                b[j][1] = Bb[n * BST2 + ck + 4];
            }
#pragma unroll
            for (int i = 0; i < 4; i++)
#pragma unroll
                for (int j = 0; j < 4; j++) mma_f16(acc[i][j], a[i], b[j]);
        }

        // end of a pass -> fp16 epilogue + reset accum (register-local, no sync)
        if (kc == 7) {
            const float* bias = (p < 2) ? bk : bv;
            __half* Cout = (p < 2) ? Kout : Vout;
            const int nh = p & 1;
            const int colw = nh * 128 + wn * 32 + (lane & 3) * 2;
            const size_t rowb = (size_t)bm * 128 + wm * 64 + (lane >> 2);
#pragma unroll
            for (int j = 0; j < 4; j++) {
                const float2 bb = *(const float2*)&bias[colw + j * 8];
#pragma unroll
                for (int i = 0; i < 4; i++) {
                    const size_t r0 = rowb + i * 16;
                    uint32_t u0 = h2u(fmaxf(acc[i][j][0] + bb.x, 0.0f),
                                      fmaxf(acc[i][j][1] + bb.y, 0.0f));
                    uint32_t u1 = h2u(fmaxf(acc[i][j][2] + bb.x, 0.0f),
                                      fmaxf(acc[i][j][3] + bb.y, 0.0f));
                    *(uint32_t*)&Cout[r0 * HID + colw + j * 8] = u0;
                    *(uint32_t*)&Cout[(r0 + 8) * HID + colw + j * 8] = u1;
#pragma unroll
                    for (int t = 0; t < 4; t++) acc[i][j][t] = 0.0f;
                }
            }
        }
    }
}

// ======================= fp32 FFMA GEMM, 64x64 tiles (Q, final) =======================
__device__ __forceinline__ unsigned long long pk2(float x, float y) {
    unsigned long long r;
    asm("mov.b64 %0,{%1,%2};" : "=l"(r) : "f"(x), "f"(y));
    return r;
}
__device__ __forceinline__ void upk2(unsigned long long v, float& x, float& y) {
    asm("mov.b64 {%0,%1},%2;" : "=f"(x), "=f"(y) : "l"(v));
}
__device__ __forceinline__ void ffma2(unsigned long long& d, unsigned long long a, unsigned long long b) {
    asm("fma.rn.f32x2 %0,%1,%2,%0;" : "+l"(d) : "l"(a), "l"(b));
}

__global__ __launch_bounds__(128, 6) void gemm_s(
    const float* __restrict__ A, const float* __restrict__ W,
    const float* __restrict__ bias, float* __restrict__ C,
    int doRelu, float scale)
{
    __shared__ float As[16][64];
    __shared__ float Bs[16][64];

    const int tid = threadIdx.x;
    const int bm = blockIdx.y, bn = blockIdx.x;
    const int tx = tid & 7, ty = tid >> 3;       // compute: rows ty*4.., cols tx*8..
    const int r0 = tid & 63, c0 = (tid >> 6) * 8; // staging: row r0, cols c0..c0+7

    const float* Ag = A + (size_t)(bm * 64 + r0) * HID + c0;
    const float* Wg = W + (size_t)(bn * 64 + r0) * HID + c0;

    unsigned long long acc[4][4];
#pragma unroll
    for (int i = 0; i < 4; i++)
#pragma unroll
        for (int j = 0; j < 4; j++) acc[i][j] = 0ull;

    for (int kt = 0; kt < 16; kt++) {
        const int k0 = kt * 16;
        {
            float4 a1 = *(const float4*)(Ag + k0);
            float4 a2 = *(const float4*)(Ag + k0 + 4);
            As[c0 + 0][r0] = a1.x; As[c0 + 1][r0] = a1.y;
            As[c0 + 2][r0] = a1.z; As[c0 + 3][r0] = a1.w;
            As[c0 + 4][r0] = a2.x; As[c0 + 5][r0] = a2.y;
            As[c0 + 6][r0] = a2.z; As[c0 + 7][r0] = a2.w;
            float4 w1 = *(const float4*)(Wg + k0);
            float4 w2 = *(const float4*)(Wg + k0 + 4);
            Bs[c0 + 0][r0] = w1.x; Bs[c0 + 1][r0] = w1.y;
            Bs[c0 + 2][r0] = w1.z; Bs[c0 + 3][r0] = w1.w;
            Bs[c0 + 4][r0] = w2.x; Bs[c0 + 5][r0] = w2.y;
            Bs[c0 + 6][r0] = w2.z; Bs[c0 + 7][r0] = w2.w;
        }
        __syncthreads();
#pragma unroll
        for (int kk = 0; kk < 16; kk++) {
            float a[4];
            *(float4*)&a[0] = *(const float4*)&As[kk][ty * 4];
            unsigned long long bb[4];
#pragma unroll
            for (int j = 0; j < 4; j++)
                bb[j] = *(const unsigned long long*)&Bs[kk][tx * 8 + 2 * j];
#pragma unroll
            for (int i = 0; i < 4; i++) {
                unsigned long long aa = pk2(a[i], a[i]);
#pragma unroll
                for (int j = 0; j < 4; j++) ffma2(acc[i][j], aa, bb[j]);
            }
        }
        __syncthreads();
    }

    const int col = bn * 64 + tx * 8;
    float bvv[8];
#pragma unroll
    for (int j = 0; j < 8; j++) bvv[j] = bias[col + j];

#pragma unroll
    for (int i = 0; i < 4; i++) {
        float out[8];
#pragma unroll
        for (int j = 0; j < 4; j++) {
            float x, y;
            upk2(acc[i][j], x, y);
            out[2 * j] = x + bvv[2 * j];
            out[2 * j + 1] = y + bvv[2 * j + 1];
        }
        if (doRelu) {
#pragma unroll
            for (int j = 0; j < 8; j++) out[j] = fmaxf(out[j], 0.0f);
        }
#pragma unroll
        for (int j = 0; j < 8; j++) out[j] *= scale;
        const int rowi = bm * 64 + ty * 4 + i;
        *(float4*)&C[(size_t)rowi * HID + col] = make_float4(out[0], out[1], out[2], out[3]);
        *(float4*)&C[(size_t)rowi * HID + col + 4] = make_float4(out[4], out[5], out[6], out[7]);
    }
}

// ======================= attention: 1 CTA / sample, fp16 K/V =======================
__global__ __launch_bounds__(256) void attn3(
    const float* __restrict__ Q, const __half* __restrict__ K,
    const __half* __restrict__ V, const int* __restrict__ starts,
    const int* __restrict__ ends, float* __restrict__ O)
{
    __shared__ float qs[256];
    __shared__ float sc[256];

    const int tid = threadIdx.x;
    const int lane = tid & 31;
    const int wid = tid >> 5;
    const int b = blockIdx.x;
    const int st = starts[b];
    const int len = ends[b] - st;     // 1..64

    qs[tid] = Q[(size_t)b * HID + tid];
    sc[tid] = -1e30f;
    __syncthreads();

    float4 q0 = *(const float4*)&qs[lane * 8];
    float4 q1 = *(const float4*)&qs[lane * 8 + 4];
    const int head = lane >> 3;

    // scores: warp w rows m = w, w+8, ..; lane loads 8 halfs (one LDG.128)
#pragma unroll
    for (int rr = 0; rr < 8; rr++) {
        const int m = rr * 8 + wid;
        if (m < len) {
            uint4 raw = *(const uint4*)(K + (size_t)(st + m) * HID + lane * 8);
            float2 f0 = __half22float2(*(__half2*)&raw.x);
            float2 f1 = __half22float2(*(__half2*)&raw.y);
            float2 f2 = __half22float2(*(__half2*)&raw.z);
            float2 f3 = __half22float2(*(__half2*)&raw.w);
            float p = q0.x * f0.x + q0.y * f0.y + q0.z * f1.x + q0.w * f1.y
                    + q1.x * f2.x + q1.y * f2.y + q1.z * f3.x + q1.w * f3.y;
            p += __shfl_down_sync(0xffffffffu, p, 4);
            p += __shfl_down_sync(0xffffffffu, p, 2);
            p += __shfl_down_sync(0xffffffffu, p, 1);
            if ((lane & 7) == 0) sc[head * 64 + m] = p;
        }
    }
    __syncthreads();

    // softmax: warp w -> head w (first 4 warps)
    if (tid < 128) {
        const int h = tid >> 5, l = tid & 31;
        float v0 = sc[h * 64 + l];
        float v1 = sc[h * 64 + 32 + l];
        float mx = fmaxf(v0, v1);
#pragma unroll
        for (int off = 16; off > 0; off >>= 1)
            mx = fmaxf(mx, __shfl_xor_sync(0xffffffffu, mx, off));
        float e0 = __expf(v0 - mx);
        float e1 = __expf(v1 - mx);
        float sum = e0 + e1;
#pragma unroll
        for (int off = 16; off > 0; off >>= 1)
            sum += __shfl_xor_sync(0xffffffffu, sum, off);
        float inv = 1.0f / sum;
        sc[h * 64 + l] = e0 * inv;
        sc[h * 64 + 32 + l] = e1 * inv;
    }
    __syncthreads();

    // out: thread = output channel, V streamed from gmem coalesced (fp16)
    {
        const int h = tid >> 6;
        const __half* vp = V + (size_t)st * HID + tid;
        const float* ap = &sc[h * 64];
        float o = 0.0f;
        int m = 0;
        for (; m + 4 <= len; m += 4) {
            float a0 = ap[m], a1 = ap[m + 1], a2 = ap[m + 2], a3 = ap[m + 3];
            float v0 = __half2float(vp[(size_t)m * HID]);
            float v1 = __half2float(vp[(size_t)(m + 1) * HID]);
            float v2 = __half2float(vp[(size_t)(m + 2) * HID]);
            float v3 = __half2float(vp[(size_t)(m + 3) * HID]);
            o = fmaf(a0, v0, o); o = fmaf(a1, v1, o);
            o = fmaf(a2, v2, o); o = fmaf(a3, v3, o);
        }
        for (; m < len; m++) o = fmaf(ap[m], __half2float(vp[(size_t)m * HID]), o);
        O[(size_t)b * HID + tid] = o;
    }
}

// ======================= launch =======================
extern "C" void kernel_launch(void* const* d_in, const int* in_sizes, int n_in,
                              void* d_out, int out_size)
{
    const float* enc = (const float*)d_in[0];
    const float* soc = (const float*)d_in[1];
    const float* Wq = (const float*)d_in[2];
    const float* bq = (const float*)d_in[3];
    const float* Wk = (const float*)d_in[4];
    const float* bk = (const float*)d_in[5];
    const float* Wv = (const float*)d_in[6];
    const float* bv = (const float*)d_in[7];
    const float* Wf = (const float*)d_in[8];
    const float* bf = (const float*)d_in[9];
    const int* st = (const int*)d_in[10];
    const int* en = (const int*)d_in[11];
    float* out = (float*)d_out;

    float *qp, *op;
    __half *kp, *vp;
    cudaGetSymbolAddress((void**)&qp, g_Q);
    cudaGetSymbolAddress((void**)&kp, g_K);
    cudaGetSymbolAddress((void**)&vp, g_V);
    cudaGetSymbolAddress((void**)&op, g_O);

    cudaFuncSetAttribute(kv_mma, cudaFuncAttributeMaxDynamicSharedMemorySize, KV_SMEM);

    // Q = relu(enc @ Wq^T + bq) / 16
    gemm_s<<<dim3(4, NB / 64), 128>>>(enc, Wq, bq, qp, 1, 0.0625f);
    // fused K,V = relu(soc @ W^T + b) via mma.sync fp16 (f32 accum), fp16 out
    kv_mma<<<NTOT / 128, 256, KV_SMEM>>>(soc, Wk, bk, Wv, bv, kp, vp);
    // attention
    attn3<<<NB, 256>>>(qp, kp, vp, st, en, op);
    // final projection (no relu)
    gemm_s<<<dim3(4, NB / 64), 128>>>(op, Wf, bf, out, 0, 1.0f);
}

// round 7
// speedup vs baseline: 5.0374x; 1.2621x over previous
#include <cuda_runtime.h>
#include <cuda_fp16.h>
#include <cstdint>

#define HID 256
#define NB 4096
#define NTOT 131072

// Scratch (allocation-free rule: __device__ globals)
__device__ float  g_Q[(size_t)NB * HID];
__device__ __half g_K[(size_t)NTOT * HID];
__device__ __half g_V[(size_t)NTOT * HID];
__device__ __half g_O[(size_t)NB * HID];

// ======================= fp16 mma helper =======================
__device__ __forceinline__ void mma_f16(float* d, const uint32_t* a, const uint32_t* b) {
    asm volatile(
        "mma.sync.aligned.m16n8k16.row.col.f32.f16.f16.f32 "
        "{%0,%1,%2,%3},{%4,%5,%6,%7},{%8,%9},{%0,%1,%2,%3};"
        : "+f"(d[0]), "+f"(d[1]), "+f"(d[2]), "+f"(d[3])
        : "r"(a[0]), "r"(a[1]), "r"(a[2]), "r"(a[3]), "r"(b[0]), "r"(b[1]));
}
__device__ __forceinline__ uint32_t h2u(float lo, float hi) {
    __half2 h = __floats2half2_rn(lo, hi);
    return *(uint32_t*)&h;
}

#define AST2 132
#define BST2 20
#define KV_SMEM ((128 * AST2 + 2 * 128 * BST2) * 4)

// ============ fused K+V+Q projections (mma.sync fp16, f32 accum) ============
// Blocks 0..1023: KV mode — A = soc rows, 4 passes (Wk n-lo, Wk n-hi, Wv n-lo,
// Wv n-hi), fp16 outputs to Kout/Vout.
// Blocks 1024..1055: Q mode — A = enc rows, 2 passes (Wq n-lo, Wq n-hi),
// relu * 1/16, fp32 output to Qout.
__global__ void __launch_bounds__(256, 2)
kvq_mma(const float* __restrict__ soc, const float* __restrict__ enc,
        const float* __restrict__ Wk, const float* __restrict__ bk,
        const float* __restrict__ Wv, const float* __restrict__ bv,
        const float* __restrict__ Wq, const float* __restrict__ bq,
        __half* __restrict__ Kout, __half* __restrict__ Vout,
        float* __restrict__ Qout)
{
    extern __shared__ uint32_t sm32[];
    uint32_t* As = sm32;                  // 128 * 132 half2 words
    uint32_t* Bs = sm32 + 128 * AST2;     // 2 buffers of 128 * 20 half2 words

    const int tid = threadIdx.x;
    const int lane = tid & 31;
    const int wid = tid >> 5;
    const int wm = wid & 1;               // m half (64 rows)
    const int wn = wid >> 1;              // n quarter (32 cols)
    const int bm = blockIdx.x;
    const bool isQ = (bm >= NTOT / 128);
    const int rowblk = isQ ? (bm - NTOT / 128) : bm;
    const int npass = isQ ? 2 : 4;

    // ---- stage A tile 128x256 -> fp16 ----
    const float* Ab = (isQ ? enc : soc) + (size_t)rowblk * 128 * HID;
#pragma unroll
    for (int i = 0; i < 32; i++) {
        int idx = i * 256 + tid;
        int r = idx >> 6, c4 = (idx & 63) << 2;
        float4 v = *(const float4*)(Ab + (size_t)r * HID + c4);
        uint2 h;
        h.x = h2u(v.x, v.y);
        h.y = h2u(v.z, v.w);
        *(uint2*)&As[r * AST2 + (c4 >> 1)] = h;
    }

    // ---- prefetch B chunk 0 ----
    const float* W0 = isQ ? Wq : Wk;
    float4 pf[4];
    {
        const int k = (tid & 7) * 4;
        const int nb = tid >> 3;
#pragma unroll
        for (int q = 0; q < 4; q++)
            pf[q] = *(const float4*)&W0[(size_t)(nb + q * 32) * HID + k];
    }

    float acc[4][4][4];
#pragma unroll
    for (int i = 0; i < 4; i++)
#pragma unroll
        for (int j = 0; j < 4; j++)
#pragma unroll
            for (int t = 0; t < 4; t++) acc[i][j][t] = 0.0f;

    const int ntc_total = npass * 8;
    for (int tc = 0; tc < ntc_total; tc++) {
        const int p = tc >> 3;            // pass
        const int kc = tc & 7;            // k chunk (32 k each)
        uint32_t* Bb = Bs + (tc & 1) * (128 * BST2);

        // store prefetched chunk into Bb (fp16)
        {
            const int nloc0 = tid >> 3;
            const int c2 = (tid & 7) * 2;
#pragma unroll
            for (int q = 0; q < 4; q++) {
                uint2 h;
                h.x = h2u(pf[q].x, pf[q].y);
                h.y = h2u(pf[q].z, pf[q].w);
                *(uint2*)&Bb[(nloc0 + q * 32) * BST2 + c2] = h;
            }
        }
        __syncthreads();

        // prefetch next chunk
        if (tc < ntc_total - 1) {
            const int ntc = tc + 1;
            const int np = ntc >> 3, nkc = ntc & 7;
            const float* W = isQ ? Wq : ((np < 2) ? Wk : Wv);
            const int nh = np & 1;
            const int k = nkc * 32 + (tid & 7) * 4;
            const int nb = nh * 128 + (tid >> 3);
#pragma unroll
            for (int q = 0; q < 4; q++)
                pf[q] = *(const float4*)&W[(size_t)(nb + q * 32) * HID + k];
        }

        // mma: 2 k16 steps per 32-k chunk
#pragma unroll
        for (int ks = 0; ks < 2; ks++) {
            const int kb = kc * 16 + ks * 8;   // half2 base in As
            uint32_t a[4][4];
#pragma unroll
            for (int i = 0; i < 4; i++) {
                const int r = wm * 64 + i * 16 + (lane >> 2);
                const int c = kb + (lane & 3);
                a[i][0] = As[r * AST2 + c];
                a[i][1] = As[(r + 8) * AST2 + c];
                a[i][2] = As[r * AST2 + c + 4];
                a[i][3] = As[(r + 8) * AST2 + c + 4];
            }
            uint32_t b[4][2];
            const int ck = ks * 8 + (lane & 3);
#pragma unroll
            for (int j = 0; j < 4; j++) {
                const int n = wn * 32 + j * 8 + (lane >> 2);
                b[j][0] = Bb[n * BST2 + ck];
                b[j][1] = Bb[n * BST2 + ck + 4];
            }
#pragma unroll
            for (int i = 0; i < 4; i++)
#pragma unroll
                for (int j = 0; j < 4; j++) mma_f16(acc[i][j], a[i], b[j]);
        }

        // end of a pass -> epilogue + reset accum
        if (kc == 7) {
            const int nh = p & 1;
            const int colw = nh * 128 + wn * 32 + (lane & 3) * 2;
            const size_t rowb = (size_t)rowblk * 128 + wm * 64 + (lane >> 2);
            if (isQ) {
                const float2 scl = make_float2(0.0625f, 0.0625f);
#pragma unroll
                for (int j = 0; j < 4; j++) {
                    const float2 bb = *(const float2*)&bq[colw + j * 8];
#pragma unroll
                    for (int i = 0; i < 4; i++) {
                        const size_t r0 = rowb + i * 16;
                        float2 o0, o1;
                        o0.x = fmaxf(acc[i][j][0] + bb.x, 0.0f) * scl.x;
                        o0.y = fmaxf(acc[i][j][1] + bb.y, 0.0f) * scl.y;
                        o1.x = fmaxf(acc[i][j][2] + bb.x, 0.0f) * scl.x;
                        o1.y = fmaxf(acc[i][j][3] + bb.y, 0.0f) * scl.y;
                        *(float2*)&Qout[r0 * HID + colw + j * 8] = o0;
                        *(float2*)&Qout[(r0 + 8) * HID + colw + j * 8] = o1;
#pragma unroll
                        for (int t = 0; t < 4; t++) acc[i][j][t] = 0.0f;
                    }
                }
            } else {
                const float* bias = (p < 2) ? bk : bv;
                __half* Cout = (p < 2) ? Kout : Vout;
#pragma unroll
                for (int j = 0; j < 4; j++) {
                    const float2 bb = *(const float2*)&bias[colw + j * 8];
#pragma unroll
                    for (int i = 0; i < 4; i++) {
                        const size_t r0 = rowb + i * 16;
                        uint32_t u0 = h2u(fmaxf(acc[i][j][0] + bb.x, 0.0f),
                                          fmaxf(acc[i][j][1] + bb.y, 0.0f));
                        uint32_t u1 = h2u(fmaxf(acc[i][j][2] + bb.x, 0.0f),
                                          fmaxf(acc[i][j][3] + bb.y, 0.0f));
                        *(uint32_t*)&Cout[r0 * HID + colw + j * 8] = u0;
                        *(uint32_t*)&Cout[(r0 + 8) * HID + colw + j * 8] = u1;
#pragma unroll
                        for (int t = 0; t < 4; t++) acc[i][j][t] = 0.0f;
                    }
                }
            }
        }
    }
}

// ============ final projection (mma.sync fp16): out = O(fp16) @ Wf^T + bf ============
// 32 CTAs of 128 rows, 256 threads, 2 passes over the 128-col halves of Wf.
__global__ void __launch_bounds__(256, 2)
fin_mma(const __half* __restrict__ O, const float* __restrict__ Wf,
        const float* __restrict__ bf, float* __restrict__ out)
{
    extern __shared__ uint32_t sm32[];
    uint32_t* As = sm32;
    uint32_t* Bs = sm32 + 128 * AST2;

    const int tid = threadIdx.x;
    const int lane = tid & 31;
    const int wid = tid >> 5;
    const int wm = wid & 1;
    const int wn = wid >> 1;
    const int bm = blockIdx.x;

    // ---- stage A tile 128x256 (already fp16) ----
    const __half* Ab = O + (size_t)bm * 128 * HID;
#pragma unroll
    for (int i = 0; i < 16; i++) {
        int idx = i * 256 + tid;            // uint4 chunk id (8 halfs)
        int r = idx >> 5, c2 = (idx & 31) * 4;
        uint4 v = *(const uint4*)(Ab + (size_t)r * HID + c2 * 2);
        *(uint4*)&As[r * AST2 + c2] = v;
    }

    float4 pf[4];
    {
        const int k = (tid & 7) * 4;
        const int nb = tid >> 3;
#pragma unroll
        for (int q = 0; q < 4; q++)
            pf[q] = *(const float4*)&Wf[(size_t)(nb + q * 32) * HID + k];
    }

    float acc[4][4][4];
#pragma unroll
    for (int i = 0; i < 4; i++)
#pragma unroll
        for (int j = 0; j < 4; j++)
#pragma unroll
            for (int t = 0; t < 4; t++) acc[i][j][t] = 0.0f;

    for (int tc = 0; tc < 16; tc++) {
        const int p = tc >> 3;
        const int kc = tc & 7;
        uint32_t* Bb = Bs + (tc & 1) * (128 * BST2);

        {
            const int nloc0 = tid >> 3;
            const int c2 = (tid & 7) * 2;
#pragma unroll
            for (int q = 0; q < 4; q++) {
                uint2 h;
                h.x = h2u(pf[q].x, pf[q].y);
                h.y = h2u(pf[q].z, pf[q].w);
                *(uint2*)&Bb[(nloc0 + q * 32) * BST2 + c2] = h;
            }
        }
        __syncthreads();

        if (tc < 15) {
            const int ntc = tc + 1;
            const int np = ntc >> 3, nkc = ntc & 7;
            const int k = nkc * 32 + (tid & 7) * 4;
            const int nb = (np & 1) * 128 + (tid >> 3);
#pragma unroll
            for (int q = 0; q < 4; q++)
                pf[q] = *(const float4*)&Wf[(size_t)(nb + q * 32) * HID + k];
        }

#pragma unroll
        for (int ks = 0; ks < 2; ks++) {
            const int kb = kc * 16 + ks * 8;
            uint32_t a[4][4];
#pragma unroll
            for (int i = 0; i < 4; i++) {
                const int r = wm * 64 + i * 16 + (lane >> 2);
                const int c = kb + (lane & 3);
                a[i][0] = As[r * AST2 + c];
                a[i][1] = As[(r + 8) * AST2 + c];
                a[i][2] = As[r * AST2 + c + 4];
                a[i][3] = As[(r + 8) * AST2 + c + 4];
            }
            uint32_t b[4][2];
            const int ck = ks * 8 + (lane & 3);
#pragma unroll
            for (int j = 0; j < 4; j++) {
                const int n = wn * 32 + j * 8 + (lane >> 2);
                b[j][0] = Bb[n * BST2 + ck];
                b[j][1] = Bb[n * BST2 + ck + 4];
            }
#pragma unroll
            for (int i = 0; i < 4; i++)
#pragma unroll
                for (int j = 0; j < 4; j++) mma_f16(acc[i][j], a[i], b[j]);
        }

        if (kc == 7) {
            const int nh = p & 1;
            const int colw = nh * 128 + wn * 32 + (lane & 3) * 2;
            const size_t rowb = (size_t)bm * 128 + wm * 64 + (lane >> 2);
#pragma unroll
            for (int j = 0; j < 4; j++) {
                const float2 bb = *(const float2*)&bf[colw + j * 8];
#pragma unroll
                for (int i = 0; i < 4; i++) {
                    const size_t r0 = rowb + i * 16;
                    float2 o0, o1;
                    o0.x = acc[i][j][0] + bb.x;
                    o0.y = acc[i][j][1] + bb.y;
                    o1.x = acc[i][j][2] + bb.x;
                    o1.y = acc[i][j][3] + bb.y;
                    *(float2*)&out[r0 * HID + colw + j * 8] = o0;
                    *(float2*)&out[(r0 + 8) * HID + colw + j * 8] = o1;
#pragma unroll
                    for (int t = 0; t < 4; t++) acc[i][j][t] = 0.0f;
                }
            }
        }
    }
}

// ======================= attention: 1 CTA / sample, fp16 K/V, fp16 O ==============
__global__ __launch_bounds__(256) void attn3(
    const float* __restrict__ Q, const __half* __restrict__ K,
    const __half* __restrict__ V, const int* __restrict__ starts,
    const int* __restrict__ ends, __half* __restrict__ O)
{
    __shared__ float qs[256];
    __shared__ float sc[256];

    const int tid = threadIdx.x;
    const int lane = tid & 31;
    const int wid = tid >> 5;
    const int b = blockIdx.x;
    const int st = starts[b];
    const int len = ends[b] - st;     // 1..64

    qs[tid] = Q[(size_t)b * HID + tid];
    sc[tid] = -1e30f;
    __syncthreads();

    float4 q0 = *(const float4*)&qs[lane * 8];
    float4 q1 = *(const float4*)&qs[lane * 8 + 4];
    const int head = lane >> 3;

    // scores
#pragma unroll
    for (int rr = 0; rr < 8; rr++) {
        const int m = rr * 8 + wid;
        if (m < len) {
            uint4 raw = *(const uint4*)(K + (size_t)(st + m) * HID + lane * 8);
            float2 f0 = __half22float2(*(__half2*)&raw.x);
            float2 f1 = __half22float2(*(__half2*)&raw.y);
            float2 f2 = __half22float2(*(__half2*)&raw.z);
            float2 f3 = __half22float2(*(__half2*)&raw.w);
            float p = q0.x * f0.x + q0.y * f0.y + q0.z * f1.x + q0.w * f1.y
                    + q1.x * f2.x + q1.y * f2.y + q1.z * f3.x + q1.w * f3.y;
            p += __shfl_down_sync(0xffffffffu, p, 4);
            p += __shfl_down_sync(0xffffffffu, p, 2);
            p += __shfl_down_sync(0xffffffffu, p, 1);
            if ((lane & 7) == 0) sc[head * 64 + m] = p;
        }
    }
    __syncthreads();

    // softmax
    if (tid < 128) {
        const int h = tid >> 5, l = tid & 31;
        float v0 = sc[h * 64 + l];
        float v1 = sc[h * 64 + 32 + l];
        float mx = fmaxf(v0, v1);
#pragma unroll
        for (int off = 16; off > 0; off >>= 1)
            mx = fmaxf(mx, __shfl_xor_sync(0xffffffffu, mx, off));
        float e0 = __expf(v0 - mx);
        float e1 = __expf(v1 - mx);
        float sum = e0 + e1;
#pragma unroll
        for (int off = 16; off > 0; off >>= 1)
            sum += __shfl_xor_sync(0xffffffffu, sum, off);
        float inv = 1.0f / sum;
        sc[h * 64 + l] = e0 * inv;
        sc[h * 64 + 32 + l] = e1 * inv;
    }
    __syncthreads();

    // out (fp16 store)
    {
        const int h = tid >> 6;
        const __half* vp = V + (size_t)st * HID + tid;
        const float* ap = &sc[h * 64];
        float o = 0.0f;
        int m = 0;
        for (; m + 4 <= len; m += 4) {
            float a0 = ap[m], a1 = ap[m + 1], a2 = ap[m + 2], a3 = ap[m + 3];
            float v0 = __half2float(vp[(size_t)m * HID]);
            float v1 = __half2float(vp[(size_t)(m + 1) * HID]);
            float v2 = __half2float(vp[(size_t)(m + 2) * HID]);
            float v3 = __half2float(vp[(size_t)(m + 3) * HID]);
            o = fmaf(a0, v0, o); o = fmaf(a1, v1, o);
            o = fmaf(a2, v2, o); o = fmaf(a3, v3, o);
        }
        for (; m < len; m++) o = fmaf(ap[m], __half2float(vp[(size_t)m * HID]), o);
        O[(size_t)b * HID + tid] = __float2half(o);
    }
}

// ======================= launch =======================
extern "C" void kernel_launch(void* const* d_in, const int* in_sizes, int n_in,
                              void* d_out, int out_size)
{
    const float* enc = (const float*)d_in[0];
    const float* soc = (const float*)d_in[1];
    const float* Wq = (const float*)d_in[2];
    const float* bq = (const float*)d_in[3];
    const float* Wk = (const float*)d_in[4];
    const float* bk = (const float*)d_in[5];
    const float* Wv = (const float*)d_in[6];
    const float* bv = (const float*)d_in[7];
    const float* Wf = (const float*)d_in[8];
    const float* bf = (const float*)d_in[9];
    const int* st = (const int*)d_in[10];
    const int* en = (const int*)d_in[11];
    float* out = (float*)d_out;

    float* qp;
    __half *kp, *vp, *op;
    cudaGetSymbolAddress((void**)&qp, g_Q);
    cudaGetSymbolAddress((void**)&kp, g_K);
    cudaGetSymbolAddress((void**)&vp, g_V);
    cudaGetSymbolAddress((void**)&op, g_O);

    cudaFuncSetAttribute(kvq_mma, cudaFuncAttributeMaxDynamicSharedMemorySize, KV_SMEM);
    cudaFuncSetAttribute(fin_mma, cudaFuncAttributeMaxDynamicSharedMemorySize, KV_SMEM);

    // fused K,V,Q projections
    kvq_mma<<<NTOT / 128 + NB / 128, 256, KV_SMEM>>>(
        soc, enc, Wk, bk, Wv, bv, Wq, bq, kp, vp, qp);
    // attention (fp16 O out)
    attn3<<<NB, 256>>>(qp, kp, vp, st, en, op);
    // final projection via fp16 mma
    fin_mma<<<NB / 128, 256, KV_SMEM>>>(op, Wf, bf, out);
}

// round 8
// speedup vs baseline: 5.2896x; 1.0501x over previous
#include <cuda_runtime.h>
#include <cuda_fp16.h>
#include <cstdint>

#define HID 256
#define NB 4096
#define NTOT 131072

// Scratch (allocation-free rule: __device__ globals)
__device__ float  g_Q[(size_t)NB * HID];
__device__ __half g_K[(size_t)NTOT * HID];
__device__ __half g_V[(size_t)NTOT * HID];
__device__ __half g_O[(size_t)NB * HID];

// ======================= helpers =======================
__device__ __forceinline__ void mma_f16(float* d, const uint32_t* a, const uint32_t* b) {
    asm volatile(
        "mma.sync.aligned.m16n8k16.row.col.f32.f16.f16.f32 "
        "{%0,%1,%2,%3},{%4,%5,%6,%7},{%8,%9},{%0,%1,%2,%3};"
        : "+f"(d[0]), "+f"(d[1]), "+f"(d[2]), "+f"(d[3])
        : "r"(a[0]), "r"(a[1]), "r"(a[2]), "r"(a[3]), "r"(b[0]), "r"(b[1]));
}
__device__ __forceinline__ uint32_t h2u(float lo, float hi) {
    __half2 h = __floats2half2_rn(lo, hi);
    return *(uint32_t*)&h;
}
__device__ __forceinline__ uint32_t smem_u32(const void* p) {
    return (uint32_t)__cvta_generic_to_shared(p);
}
__device__ __forceinline__ void ldsm_x4(uint32_t& r0, uint32_t& r1, uint32_t& r2, uint32_t& r3,
                                        uint32_t addr) {
    asm volatile("ldmatrix.sync.aligned.m8n8.x4.shared.b16 {%0,%1,%2,%3}, [%4];"
                 : "=r"(r0), "=r"(r1), "=r"(r2), "=r"(r3) : "r"(addr));
}

#define AST2 132
#define BST2 20
#define KV_SMEM ((128 * AST2 + 2 * 128 * BST2) * 4)

// ============ fused K+V+Q projections (mma.sync fp16, f32 accum, LDSM frags) ========
// Blocks 0..1023: KV mode (A = soc, 4 passes: Wk-lo, Wk-hi, Wv-lo, Wv-hi -> fp16).
// Blocks 1024..1055: Q mode (A = enc, 2 passes over Wq, relu/16 -> fp32).
__global__ void __launch_bounds__(256, 2)
kvq_mma(const float* __restrict__ soc, const float* __restrict__ enc,
        const float* __restrict__ Wk, const float* __restrict__ bk,
        const float* __restrict__ Wv, const float* __restrict__ bv,
        const float* __restrict__ Wq, const float* __restrict__ bq,
        __half* __restrict__ Kout, __half* __restrict__ Vout,
        float* __restrict__ Qout)
{
    extern __shared__ uint32_t sm32[];
    uint32_t* As = sm32;                  // 128 * 132 half2 words
    uint32_t* Bs = sm32 + 128 * AST2;     // 2 buffers of 128 * 20 half2 words

    const int tid = threadIdx.x;
    const int lane = tid & 31;
    const int wid = tid >> 5;
    const int wm = wid & 1;               // m half (64 rows)
    const int wn = wid >> 1;              // n quarter (32 cols)
    const int bm = blockIdx.x;
    const bool isQ = (bm >= NTOT / 128);
    const int rowblk = isQ ? (bm - NTOT / 128) : bm;
    const int npass = isQ ? 2 : 4;

    // LDSM lane address components
    const uint32_t Abase = smem_u32(As);
    const uint32_t Bbase = smem_u32(Bs);
    const int arow = wm * 64 + (lane & 15);
    const int acol = (lane >> 4) << 2;                       // 0 or 4 words
    const int brow = wn * 32 + ((lane >> 4) << 3) + (lane & 7);
    const int bcol = ((lane >> 3) & 1) << 2;                 // 0 or 4 words

    // ---- stage A tile 128x256 -> fp16 ----
    const float* Ab = (isQ ? enc : soc) + (size_t)rowblk * 128 * HID;
#pragma unroll
    for (int i = 0; i < 32; i++) {
        int idx = i * 256 + tid;
        int r = idx >> 6, c4 = (idx & 63) << 2;
        float4 v = *(const float4*)(Ab + (size_t)r * HID + c4);
        uint2 h;
        h.x = h2u(v.x, v.y);
        h.y = h2u(v.z, v.w);
        *(uint2*)&As[r * AST2 + (c4 >> 1)] = h;
    }

    // ---- prefetch B chunk 0 ----
    const float* W0 = isQ ? Wq : Wk;
    float4 pf[4];
    {
        const int k = (tid & 7) * 4;
        const int nb = tid >> 3;
#pragma unroll
        for (int q = 0; q < 4; q++)
            pf[q] = *(const float4*)&W0[(size_t)(nb + q * 32) * HID + k];
    }

    float acc[4][4][4];
#pragma unroll
    for (int i = 0; i < 4; i++)
#pragma unroll
        for (int j = 0; j < 4; j++)
#pragma unroll
            for (int t = 0; t < 4; t++) acc[i][j][t] = 0.0f;

    const int ntc_total = npass * 8;
    for (int tc = 0; tc < ntc_total; tc++) {
        const int p = tc >> 3;            // pass
        const int kc = tc & 7;            // k chunk (32 k each)
        const int bufofs = (tc & 1) * (128 * BST2);
        uint32_t* Bb = Bs + bufofs;

        // store prefetched chunk into Bb (fp16)
        {
            const int nloc0 = tid >> 3;
            const int c2 = (tid & 7) * 2;
#pragma unroll
            for (int q = 0; q < 4; q++) {
                uint2 h;
                h.x = h2u(pf[q].x, pf[q].y);
                h.y = h2u(pf[q].z, pf[q].w);
                *(uint2*)&Bb[(nloc0 + q * 32) * BST2 + c2] = h;
            }
        }
        __syncthreads();

        // prefetch next chunk
        if (tc < ntc_total - 1) {
            const int ntc = tc + 1;
            const int np = ntc >> 3, nkc = ntc & 7;
            const float* W = isQ ? Wq : ((np < 2) ? Wk : Wv);
            const int nh = np & 1;
            const int k = nkc * 32 + (tid & 7) * 4;
            const int nb = nh * 128 + (tid >> 3);
#pragma unroll
            for (int q = 0; q < 4; q++)
                pf[q] = *(const float4*)&W[(size_t)(nb + q * 32) * HID + k];
        }

        // mma: 2 k16 steps per 32-k chunk, LDSM fragment loads
        const uint32_t Bb32 = Bbase + bufofs * 4;
#pragma unroll
        for (int ks = 0; ks < 2; ks++) {
            const int kb = kc * 16 + ks * 8;   // half2 word base in As
            uint32_t a[4][4];
#pragma unroll
            for (int i = 0; i < 4; i++)
                ldsm_x4(a[i][0], a[i][1], a[i][2], a[i][3],
                        Abase + (uint32_t)(((arow + i * 16) * AST2 + kb + acol) * 4));
            uint32_t b[4][2];
            const int bk0 = ks * 8 + bcol;
            ldsm_x4(b[0][0], b[0][1], b[1][0], b[1][1],
                    Bb32 + (uint32_t)((brow * BST2 + bk0) * 4));
            ldsm_x4(b[2][0], b[2][1], b[3][0], b[3][1],
                    Bb32 + (uint32_t)(((brow + 16) * BST2 + bk0) * 4));
#pragma unroll
            for (int i = 0; i < 4; i++)
#pragma unroll
                for (int j = 0; j < 4; j++) mma_f16(acc[i][j], a[i], b[j]);
        }

        // end of a pass -> epilogue + reset accum
        if (kc == 7) {
            const int nh = p & 1;
            const int colw = nh * 128 + wn * 32 + (lane & 3) * 2;
            const size_t rowb = (size_t)rowblk * 128 + wm * 64 + (lane >> 2);
            if (isQ) {
#pragma unroll
                for (int j = 0; j < 4; j++) {
                    const float2 bb = *(const float2*)&bq[colw + j * 8];
#pragma unroll
                    for (int i = 0; i < 4; i++) {
                        const size_t r0 = rowb + i * 16;
                        float2 o0, o1;
                        o0.x = fmaxf(acc[i][j][0] + bb.x, 0.0f) * 0.0625f;
                        o0.y = fmaxf(acc[i][j][1] + bb.y, 0.0f) * 0.0625f;
                        o1.x = fmaxf(acc[i][j][2] + bb.x, 0.0f) * 0.0625f;
                        o1.y = fmaxf(acc[i][j][3] + bb.y, 0.0f) * 0.0625f;
                        *(float2*)&Qout[r0 * HID + colw + j * 8] = o0;
                        *(float2*)&Qout[(r0 + 8) * HID + colw + j * 8] = o1;
#pragma unroll
                        for (int t = 0; t < 4; t++) acc[i][j][t] = 0.0f;
                    }
                }
            } else {
                const float* bias = (p < 2) ? bk : bv;
                __half* Cout = (p < 2) ? Kout : Vout;
#pragma unroll
                for (int j = 0; j < 4; j++) {
                    const float2 bb = *(const float2*)&bias[colw + j * 8];
#pragma unroll
                    for (int i = 0; i < 4; i++) {
                        const size_t r0 = rowb + i * 16;
                        uint32_t u0 = h2u(fmaxf(acc[i][j][0] + bb.x, 0.0f),
                                          fmaxf(acc[i][j][1] + bb.y, 0.0f));
                        uint32_t u1 = h2u(fmaxf(acc[i][j][2] + bb.x, 0.0f),
                                          fmaxf(acc[i][j][3] + bb.y, 0.0f));
                        *(uint32_t*)&Cout[r0 * HID + colw + j * 8] = u0;
                        *(uint32_t*)&Cout[(r0 + 8) * HID + colw + j * 8] = u1;
#pragma unroll
                        for (int t = 0; t < 4; t++) acc[i][j][t] = 0.0f;
                    }
                }
            }
        }
    }
}

// ============ final projection (mma.sync fp16, LDSM): out = O @ Wf^T + bf ============
__global__ void __launch_bounds__(256, 2)
fin_mma(const __half* __restrict__ O, const float* __restrict__ Wf,
        const float* __restrict__ bf, float* __restrict__ out)
{
    extern __shared__ uint32_t sm32[];
    uint32_t* As = sm32;
    uint32_t* Bs = sm32 + 128 * AST2;

    const int tid = threadIdx.x;
    const int lane = tid & 31;
    const int wid = tid >> 5;
    const int wm = wid & 1;
    const int wn = wid >> 1;
    const int bm = blockIdx.x;

    const uint32_t Abase = smem_u32(As);
    const uint32_t Bbase = smem_u32(Bs);
    const int arow = wm * 64 + (lane & 15);
    const int acol = (lane >> 4) << 2;
    const int brow = wn * 32 + ((lane >> 4) << 3) + (lane & 7);
    const int bcol = ((lane >> 3) & 1) << 2;

    // ---- stage A tile 128x256 (already fp16) ----
    const __half* Ab = O + (size_t)bm * 128 * HID;
#pragma unroll
    for (int i = 0; i < 16; i++) {
        int idx = i * 256 + tid;
        int r = idx >> 5, c2 = (idx & 31) * 4;
        uint4 v = *(const uint4*)(Ab + (size_t)r * HID + c2 * 2);
        *(uint4*)&As[r * AST2 + c2] = v;
    }

    float4 pf[4];
    {
        const int k = (tid & 7) * 4;
        const int nb = tid >> 3;
#pragma unroll
        for (int q = 0; q < 4; q++)
            pf[q] = *(const float4*)&Wf[(size_t)(nb + q * 32) * HID + k];
    }

    float acc[4][4][4];
#pragma unroll
    for (int i = 0; i < 4; i++)
#pragma unroll
        for (int j = 0; j < 4; j++)
#pragma unroll
            for (int t = 0; t < 4; t++) acc[i][j][t] = 0.0f;

    for (int tc = 0; tc < 16; tc++) {
        const int p = tc >> 3;
        const int kc = tc & 7;
        const int bufofs = (tc & 1) * (128 * BST2);
        uint32_t* Bb = Bs + bufofs;

        {
            const int nloc0 = tid >> 3;
            const int c2 = (tid & 7) * 2;
#pragma unroll
            for (int q = 0; q < 4; q++) {
                uint2 h;
                h.x = h2u(pf[q].x, pf[q].y);
                h.y = h2u(pf[q].z, pf[q].w);
                *(uint2*)&Bb[(nloc0 + q * 32) * BST2 + c2] = h;
            }
        }
        __syncthreads();

        if (tc < 15) {
            const int ntc = tc + 1;
            const int np = ntc >> 3, nkc = ntc & 7;
            const int k = nkc * 32 + (tid & 7) * 4;
            const int nb = (np & 1) * 128 + (tid >> 3);
#pragma unroll
            for (int q = 0; q < 4; q++)
                pf[q] = *(const float4*)&Wf[(size_t)(nb + q * 32) * HID + k];
        }

        const uint32_t Bb32 = Bbase + bufofs * 4;
#pragma unroll
        for (int ks = 0; ks < 2; ks++) {
            const int kb = kc * 16 + ks * 8;
            uint32_t a[4][4];
#pragma unroll
            for (int i = 0; i < 4; i++)
                ldsm_x4(a[i][0], a[i][1], a[i][2], a[i][3],
                        Abase + (uint32_t)(((arow + i * 16) * AST2 + kb + acol) * 4));
            uint32_t b[4][2];
            const int bk0 = ks * 8 + bcol;
            ldsm_x4(b[0][0], b[0][1], b[1][0], b[1][1],
                    Bb32 + (uint32_t)((brow * BST2 + bk0) * 4));
            ldsm_x4(b[2][0], b[2][1], b[3][0], b[3][1],
                    Bb32 + (uint32_t)(((brow + 16) * BST2 + bk0) * 4));
#pragma unroll
            for (int i = 0; i < 4; i++)
#pragma unroll
                for (int j = 0; j < 4; j++) mma_f16(acc[i][j], a[i], b[j]);
        }

        if (kc == 7) {
            const int nh = p & 1;
            const int colw = nh * 128 + wn * 32 + (lane & 3) * 2;
            const size_t rowb = (size_t)bm * 128 + wm * 64 + (lane >> 2);
#pragma unroll
            for (int j = 0; j < 4; j++) {
                const float2 bb = *(const float2*)&bf[colw + j * 8];
#pragma unroll
                for (int i = 0; i < 4; i++) {
                    const size_t r0 = rowb + i * 16;
                    float2 o0, o1;
                    o0.x = acc[i][j][0] + bb.x;
                    o0.y = acc[i][j][1] + bb.y;
                    o1.x = acc[i][j][2] + bb.x;
                    o1.y = acc[i][j][3] + bb.y;
                    *(float2*)&out[r0 * HID + colw + j * 8] = o0;
                    *(float2*)&out[(r0 + 8) * HID + colw + j * 8] = o1;
#pragma unroll
                    for (int t = 0; t < 4; t++) acc[i][j][t] = 0.0f;
                }
            }
        }
    }
}

// ======================= attention: 1 CTA / sample, fp16 K/V, fp16 O ==============
__global__ __launch_bounds__(256) void attn3(
    const float* __restrict__ Q, const __half* __restrict__ K,
    const __half* __restrict__ V, const int* __restrict__ starts,
    const int* __restrict__ ends, __half* __restrict__ O)
{
    __shared__ float qs[256];
    __shared__ float sc[256];

    const int tid = threadIdx.x;
    const int lane = tid & 31;
    const int wid = tid >> 5;
    const int b = blockIdx.x;
    const int st = starts[b];
    const int len = ends[b] - st;     // 1..64

    qs[tid] = Q[(size_t)b * HID + tid];
    sc[tid] = -1e30f;
    __syncthreads();

    float4 q0 = *(const float4*)&qs[lane * 8];
    float4 q1 = *(const float4*)&qs[lane * 8 + 4];
    const int head = lane >> 3;

    // scores
#pragma unroll
    for (int rr = 0; rr < 8; rr++) {
        const int m = rr * 8 + wid;
        if (m < len) {
            uint4 raw = *(const uint4*)(K + (size_t)(st + m) * HID + lane * 8);
            float2 f0 = __half22float2(*(__half2*)&raw.x);
            float2 f1 = __half22float2(*(__half2*)&raw.y);
            float2 f2 = __half22float2(*(__half2*)&raw.z);
            float2 f3 = __half22float2(*(__half2*)&raw.w);
            float p = q0.x * f0.x + q0.y * f0.y + q0.z * f1.x + q0.w * f1.y
                    + q1.x * f2.x + q1.y * f2.y + q1.z * f3.x + q1.w * f3.y;
            p += __shfl_down_sync(0xffffffffu, p, 4);
            p += __shfl_down_sync(0xffffffffu, p, 2);
            p += __shfl_down_sync(0xffffffffu, p, 1);
            if ((lane & 7) == 0) sc[head * 64 + m] = p;
        }
    }
    __syncthreads();

    // softmax
    if (tid < 128) {
        const int h = tid >> 5, l = tid & 31;
        float v0 = sc[h * 64 + l];
        float v1 = sc[h * 64 + 32 + l];
        float mx = fmaxf(v0, v1);
#pragma unroll
        for (int off = 16; off > 0; off >>= 1)
            mx = fmaxf(mx, __shfl_xor_sync(0xffffffffu, mx, off));
        float e0 = __expf(v0 - mx);
        float e1 = __expf(v1 - mx);
        float sum = e0 + e1;
#pragma unroll
        for (int off = 16; off > 0; off >>= 1)
            sum += __shfl_xor_sync(0xffffffffu, sum, off);
        float inv = 1.0f / sum;
        sc[h * 64 + l] = e0 * inv;
        sc[h * 64 + 32 + l] = e1 * inv;
    }
    __syncthreads();

    // out (fp16 store)
    {
        const int h = tid >> 6;
        const __half* vp = V + (size_t)st * HID + tid;
        const float* ap = &sc[h * 64];
        float o = 0.0f;
        int m = 0;
        for (; m + 4 <= len; m += 4) {
            float a0 = ap[m], a1 = ap[m + 1], a2 = ap[m + 2], a3 = ap[m + 3];
            float v0 = __half2float(vp[(size_t)m * HID]);
            float v1 = __half2float(vp[(size_t)(m + 1) * HID]);
            float v2 = __half2float(vp[(size_t)(m + 2) * HID]);
            float v3 = __half2float(vp[(size_t)(m + 3) * HID]);
            o = fmaf(a0, v0, o); o = fmaf(a1, v1, o);
            o = fmaf(a2, v2, o); o = fmaf(a3, v3, o);
        }
        for (; m < len; m++) o = fmaf(ap[m], __half2float(vp[(size_t)m * HID]), o);
        O[(size_t)b * HID + tid] = __float2half(o);
    }
}

// ======================= launch =======================
extern "C" void kernel_launch(void* const* d_in, const int* in_sizes, int n_in,
                              void* d_out, int out_size)
{
    const float* enc = (const float*)d_in[0];
    const float* soc = (const float*)d_in[1];
    const float* Wq = (const float*)d_in[2];
    const float* bq = (const float*)d_in[3];
    const float* Wk = (const float*)d_in[4];
    const float* bk = (const float*)d_in[5];
    const float* Wv = (const float*)d_in[6];
    const float* bv = (const float*)d_in[7];
    const float* Wf = (const float*)d_in[8];
    const float* bf = (const float*)d_in[9];
    const int* st = (const int*)d_in[10];
    const int* en = (const int*)d_in[11];
    float* out = (float*)d_out;

    float* qp;
    __half *kp, *vp, *op;
    cudaGetSymbolAddress((void**)&qp, g_Q);
    cudaGetSymbolAddress((void**)&kp, g_K);
    cudaGetSymbolAddress((void**)&vp, g_V);
    cudaGetSymbolAddress((void**)&op, g_O);

    cudaFuncSetAttribute(kvq_mma, cudaFuncAttributeMaxDynamicSharedMemorySize, KV_SMEM);
    cudaFuncSetAttribute(fin_mma, cudaFuncAttributeMaxDynamicSharedMemorySize, KV_SMEM);

    // fused K,V,Q projections
    kvq_mma<<<NTOT / 128 + NB / 128, 256, KV_SMEM>>>(
        soc, enc, Wk, bk, Wv, bv, Wq, bq, kp, vp, qp);
    // attention (fp16 O out)
    attn3<<<NB, 256>>>(qp, kp, vp, st, en, op);
    // final projection via fp16 mma
    fin_mma<<<NB / 128, 256, KV_SMEM>>>(op, Wf, bf, out);
}

// round 9
// speedup vs baseline: 5.3654x; 1.0143x over previous
#include <cuda_runtime.h>
#include <cuda_fp16.h>
#include <cstdint>

#define HID 256
#define NB 4096
#define NTOT 131072

// Scratch (allocation-free rule: __device__ globals)
__device__ float  g_Q[(size_t)NB * HID];
__device__ __half g_K[(size_t)NTOT * HID];
__device__ __half g_V[(size_t)NTOT * HID];
__device__ __half g_O[(size_t)NB * HID];
__device__ __half g_Wk16[HID * HID];
__device__ __half g_Wv16[HID * HID];
__device__ __half g_Wq16[HID * HID];
__device__ __half g_Wf16[HID * HID];

// ======================= helpers =======================
__device__ __forceinline__ void mma_f16(float* d, const uint32_t* a, const uint32_t* b) {
    asm volatile(
        "mma.sync.aligned.m16n8k16.row.col.f32.f16.f16.f32 "
        "{%0,%1,%2,%3},{%4,%5,%6,%7},{%8,%9},{%0,%1,%2,%3};"
        : "+f"(d[0]), "+f"(d[1]), "+f"(d[2]), "+f"(d[3])
        : "r"(a[0]), "r"(a[1]), "r"(a[2]), "r"(a[3]), "r"(b[0]), "r"(b[1]));
}
__device__ __forceinline__ uint32_t h2u(float lo, float hi) {
    __half2 h = __floats2half2_rn(lo, hi);
    return *(uint32_t*)&h;
}
__device__ __forceinline__ uint32_t smem_u32(const void* p) {
    return (uint32_t)__cvta_generic_to_shared(p);
}
__device__ __forceinline__ void ldsm_x4(uint32_t& r0, uint32_t& r1, uint32_t& r2, uint32_t& r3,
                                        uint32_t addr) {
    asm volatile("ldmatrix.sync.aligned.m8n8.x4.shared.b16 {%0,%1,%2,%3}, [%4];"
                 : "=r"(r0), "=r"(r1), "=r"(r2), "=r"(r3) : "r"(addr));
}
__device__ __forceinline__ void cpa16(uint32_t dst, const void* src) {
    asm volatile("cp.async.ca.shared.global [%0], [%1], 16;" :: "r"(dst), "l"(src));
}
__device__ __forceinline__ void cpa_commit() {
    asm volatile("cp.async.commit_group;" ::: "memory");
}
__device__ __forceinline__ void cpa_wait1() {
    asm volatile("cp.async.wait_group 1;" ::: "memory");
}

#define AST2 132
#define BST2 20
#define KV_SMEM ((128 * AST2 + 3 * 128 * BST2) * 4)

// ======== weight fp32 -> fp16 pre-conversion (once per launch) ========
__global__ void __launch_bounds__(256) w2h(
    const float* __restrict__ Wk, const float* __restrict__ Wv,
    const float* __restrict__ Wq, const float* __restrict__ Wf)
{
    const int i = blockIdx.x * 256 + threadIdx.x;   // 0..65535
    g_Wk16[i] = __float2half_rn(Wk[i]);
    g_Wv16[i] = __float2half_rn(Wv[i]);
    g_Wq16[i] = __float2half_rn(Wq[i]);
    g_Wf16[i] = __float2half_rn(Wf[i]);
}

// issue one B chunk (128 n-rows x 32 k, fp16) via cp.async into ring buffer
__device__ __forceinline__ void issue_b(const __half* W16, int nh, int kc,
                                        uint32_t bufb32, int tid) {
#pragma unroll
    for (int r = 0; r < 2; r++) {
        const int task = tid + r * 256;       // 0..511
        const int n = task >> 2;
        const int s = task & 3;               // 16B segment within 64B row
        cpa16(bufb32 + (uint32_t)((n * BST2 + s * 4) * 4),
              W16 + (size_t)(nh * 128 + n) * HID + kc * 32 + s * 8);
    }
}

// ============ fused K+V+Q projections (mma.sync fp16, cp.async B stream) ============
// Blocks 0..1023: KV mode (A = soc, 4 passes: Wk-lo, Wk-hi, Wv-lo, Wv-hi -> fp16).
// Blocks 1024..1055: Q mode (A = enc, 2 passes over Wq, relu/16 -> fp32).
__global__ void __launch_bounds__(256, 2)
kvq_mma(const float* __restrict__ soc, const float* __restrict__ enc,
        const float* __restrict__ bk, const float* __restrict__ bv,
        const float* __restrict__ bq,
        __half* __restrict__ Kout, __half* __restrict__ Vout,
        float* __restrict__ Qout)
{
    extern __shared__ uint32_t sm32[];
    uint32_t* As = sm32;                  // 128 * 132 half2 words
    const uint32_t Abase = smem_u32(As);
    const uint32_t Bbase = Abase + 128 * AST2 * 4;   // 3 ring buffers

    const int tid = threadIdx.x;
    const int lane = tid & 31;
    const int wid = tid >> 5;
    const int wm = wid & 1;               // m half (64 rows)
    const int wn = wid >> 1;              // n quarter (32 cols)
    const int bm = blockIdx.x;
    const bool isQ = (bm >= NTOT / 128);
    const int rowblk = isQ ? (bm - NTOT / 128) : bm;
    const int ntc_total = isQ ? 16 : 32;

    // LDSM lane address components
    const int arow = wm * 64 + (lane & 15);
    const int acol = (lane >> 4) << 2;
    const int brow = wn * 32 + ((lane >> 4) << 3) + (lane & 7);
    const int bcol = ((lane >> 3) & 1) << 2;

    // ---- issue B chunk 0 ----
    const __half* WK16 = isQ ? g_Wq16 : g_Wk16;
    const __half* WV16 = isQ ? g_Wq16 : g_Wv16;
    issue_b(WK16, 0, 0, Bbase, tid);
    cpa_commit();

    // ---- stage A tile 128x256 -> fp16 (overlaps with cp.async above) ----
    const float* Ab = (isQ ? enc : soc) + (size_t)rowblk * 128 * HID;
#pragma unroll
    for (int i = 0; i < 32; i++) {
        int idx = i * 256 + tid;
        int r = idx >> 6, c4 = (idx & 63) << 2;
        float4 v = *(const float4*)(Ab + (size_t)r * HID + c4);
        uint2 h;
        h.x = h2u(v.x, v.y);
        h.y = h2u(v.z, v.w);
        *(uint2*)&As[r * AST2 + (c4 >> 1)] = h;
    }

    float acc[4][4][4];
#pragma unroll
    for (int i = 0; i < 4; i++)
#pragma unroll
        for (int j = 0; j < 4; j++)
#pragma unroll
            for (int t = 0; t < 4; t++) acc[i][j][t] = 0.0f;

    for (int tc = 0; tc < ntc_total; tc++) {
        const int p = tc >> 3;            // pass
        const int kc = tc & 7;            // k chunk (32 k each)

        // issue next chunk into ring slot (tc+1)%3
        if (tc + 1 < ntc_total) {
            const int ntc = tc + 1;
            const int np = ntc >> 3, nkc = ntc & 7;
            const __half* W = (np < 2) ? WK16 : WV16;
            issue_b(W, np & 1, nkc, Bbase + (uint32_t)(((ntc) % 3) * 128 * BST2 * 4), tid);
        }
        cpa_commit();
        cpa_wait1();          // chunk tc complete, (tc+1) may be in flight
        __syncthreads();

        // mma: 2 k16 steps on ring slot tc%3
        const uint32_t Bb32 = Bbase + (uint32_t)((tc % 3) * 128 * BST2 * 4);
#pragma unroll
        for (int ks = 0; ks < 2; ks++) {
            const int kb = kc * 16 + ks * 8;
            uint32_t a[4][4];
#pragma unroll
            for (int i = 0; i < 4; i++)
                ldsm_x4(a[i][0], a[i][1], a[i][2], a[i][3],
                        Abase + (uint32_t)(((arow + i * 16) * AST2 + kb + acol) * 4));
            uint32_t b[4][2];
            const int bk0 = ks * 8 + bcol;
            ldsm_x4(b[0][0], b[0][1], b[1][0], b[1][1],
                    Bb32 + (uint32_t)((brow * BST2 + bk0) * 4));
            ldsm_x4(b[2][0], b[2][1], b[3][0], b[3][1],
                    Bb32 + (uint32_t)(((brow + 16) * BST2 + bk0) * 4));
#pragma unroll
            for (int i = 0; i < 4; i++)
#pragma unroll
                for (int j = 0; j < 4; j++) mma_f16(acc[i][j], a[i], b[j]);
        }

        // end of a pass -> epilogue + reset accum
        if (kc == 7) {
            const int nh = p & 1;
            const int colw = nh * 128 + wn * 32 + (lane & 3) * 2;
            const size_t rowb = (size_t)rowblk * 128 + wm * 64 + (lane >> 2);
            if (isQ) {
#pragma unroll
                for (int j = 0; j < 4; j++) {
                    const float2 bb = *(const float2*)&bq[colw + j * 8];
#pragma unroll
                    for (int i = 0; i < 4; i++) {
                        const size_t r0 = rowb + i * 16;
                        float2 o0, o1;
                        o0.x = fmaxf(acc[i][j][0] + bb.x, 0.0f) * 0.0625f;
                        o0.y = fmaxf(acc[i][j][1] + bb.y, 0.0f) * 0.0625f;
                        o1.x = fmaxf(acc[i][j][2] + bb.x, 0.0f) * 0.0625f;
                        o1.y = fmaxf(acc[i][j][3] + bb.y, 0.0f) * 0.0625f;
                        *(float2*)&Qout[r0 * HID + colw + j * 8] = o0;
                        *(float2*)&Qout[(r0 + 8) * HID + colw + j * 8] = o1;
#pragma unroll
                        for (int t = 0; t < 4; t++) acc[i][j][t] = 0.0f;
                    }
                }
            } else {
                const float* bias = (p < 2) ? bk : bv;
                __half* Cout = (p < 2) ? Kout : Vout;
#pragma unroll
                for (int j = 0; j < 4; j++) {
                    const float2 bb = *(const float2*)&bias[colw + j * 8];
#pragma unroll
                    for (int i = 0; i < 4; i++) {
                        const size_t r0 = rowb + i * 16;
                        uint32_t u0 = h2u(fmaxf(acc[i][j][0] + bb.x, 0.0f),
                                          fmaxf(acc[i][j][1] + bb.y, 0.0f));
                        uint32_t u1 = h2u(fmaxf(acc[i][j][2] + bb.x, 0.0f),
                                          fmaxf(acc[i][j][3] + bb.y, 0.0f));
                        *(uint32_t*)&Cout[r0 * HID + colw + j * 8] = u0;
                        *(uint32_t*)&Cout[(r0 + 8) * HID + colw + j * 8] = u1;
#pragma unroll
                        for (int t = 0; t < 4; t++) acc[i][j][t] = 0.0f;
                    }
                }
            }
        }
    }
}

// ============ final projection (mma.sync fp16, cp.async): out = O @ Wf16^T + bf ========
__global__ void __launch_bounds__(256, 2)
fin_mma(const __half* __restrict__ O, const float* __restrict__ bf,
        float* __restrict__ out)
{
    extern __shared__ uint32_t sm32[];
    uint32_t* As = sm32;
    const uint32_t Abase = smem_u32(As);
    const uint32_t Bbase = Abase + 128 * AST2 * 4;

    const int tid = threadIdx.x;
    const int lane = tid & 31;
    const int wid = tid >> 5;
    const int wm = wid & 1;
    const int wn = wid >> 1;
    const int bm = blockIdx.x;

    const int arow = wm * 64 + (lane & 15);
    const int acol = (lane >> 4) << 2;
    const int brow = wn * 32 + ((lane >> 4) << 3) + (lane & 7);
    const int bcol = ((lane >> 3) & 1) << 2;

    issue_b(g_Wf16, 0, 0, Bbase, tid);
    cpa_commit();

    // ---- stage A tile 128x256 (already fp16) ----
    const __half* Ab = O + (size_t)bm * 128 * HID;
#pragma unroll
    for (int i = 0; i < 16; i++) {
        int idx = i * 256 + tid;
        int r = idx >> 5, c2 = (idx & 31) * 4;
        uint4 v = *(const uint4*)(Ab + (size_t)r * HID + c2 * 2);
        *(uint4*)&As[r * AST2 + c2] = v;
    }

    float acc[4][4][4];
#pragma unroll
    for (int i = 0; i < 4; i++)
#pragma unroll
        for (int j = 0; j < 4; j++)
#pragma unroll
            for (int t = 0; t < 4; t++) acc[i][j][t] = 0.0f;

    for (int tc = 0; tc < 16; tc++) {
        const int p = tc >> 3;
        const int kc = tc & 7;

        if (tc + 1 < 16) {
            const int ntc = tc + 1;
            issue_b(g_Wf16, (ntc >> 3) & 1, ntc & 7,
                    Bbase + (uint32_t)((ntc % 3) * 128 * BST2 * 4), tid);
        }
        cpa_commit();
        cpa_wait1();
        __syncthreads();

        const uint32_t Bb32 = Bbase + (uint32_t)((tc % 3) * 128 * BST2 * 4);
#pragma unroll
        for (int ks = 0; ks < 2; ks++) {
            const int kb = kc * 16 + ks * 8;
            uint32_t a[4][4];
#pragma unroll
            for (int i = 0; i < 4; i++)
                ldsm_x4(a[i][0], a[i][1], a[i][2], a[i][3],
                        Abase + (uint32_t)(((arow + i * 16) * AST2 + kb + acol) * 4));
            uint32_t b[4][2];
            const int bk0 = ks * 8 + bcol;
            ldsm_x4(b[0][0], b[0][1], b[1][0], b[1][1],
                    Bb32 + (uint32_t)((brow * BST2 + bk0) * 4));
            ldsm_x4(b[2][0], b[2][1], b[3][0], b[3][1],
                    Bb32 + (uint32_t)(((brow + 16) * BST2 + bk0) * 4));
#pragma unroll
            for (int i = 0; i < 4; i++)
#pragma unroll
                for (int j = 0; j < 4; j++) mma_f16(acc[i][j], a[i], b[j]);
        }

        if (kc == 7) {
            const int nh = p & 1;
            const int colw = nh * 128 + wn * 32 + (lane & 3) * 2;
            const size_t rowb = (size_t)bm * 128 + wm * 64 + (lane >> 2);
#pragma unroll
            for (int j = 0; j < 4; j++) {
                const float2 bb = *(const float2*)&bf[colw + j * 8];
#pragma unroll
                for (int i = 0; i < 4; i++) {
                    const size_t r0 = rowb + i * 16;
                    float2 o0, o1;
                    o0.x = acc[i][j][0] + bb.x;
                    o0.y = acc[i][j][1] + bb.y;
                    o1.x = acc[i][j][2] + bb.x;
                    o1.y = acc[i][j][3] + bb.y;
                    *(float2*)&out[r0 * HID + colw + j * 8] = o0;
                    *(float2*)&out[(r0 + 8) * HID + colw + j * 8] = o1;
#pragma unroll
                    for (int t = 0; t < 4; t++) acc[i][j][t] = 0.0f;
                }
            }
        }
    }
}

// ======================= attention: 1 CTA / sample, fp16 K/V, fp16 O ==============
__global__ __launch_bounds__(256) void attn3(
    const float* __restrict__ Q, const __half* __restrict__ K,
    const __half* __restrict__ V, const int* __restrict__ starts,
    const int* __restrict__ ends, __half* __restrict__ O)
{
    __shared__ float qs[256];
    __shared__ float sc[256];

    const int tid = threadIdx.x;
    const int lane = tid & 31;
    const int wid = tid >> 5;
    const int b = blockIdx.x;
    const int st = starts[b];
    const int len = ends[b] - st;     // 1..64

    qs[tid] = Q[(size_t)b * HID + tid];
    sc[tid] = -1e30f;
    __syncthreads();

    float4 q0 = *(const float4*)&qs[lane * 8];
    float4 q1 = *(const float4*)&qs[lane * 8 + 4];
    const int head = lane >> 3;

    // scores
#pragma unroll
    for (int rr = 0; rr < 8; rr++) {
        const int m = rr * 8 + wid;
        if (m < len) {
            uint4 raw = *(const uint4*)(K + (size_t)(st + m) * HID + lane * 8);
            float2 f0 = __half22float2(*(__half2*)&raw.x);
            float2 f1 = __half22float2(*(__half2*)&raw.y);
            float2 f2 = __half22float2(*(__half2*)&raw.z);
            float2 f3 = __half22float2(*(__half2*)&raw.w);
            float p = q0.x * f0.x + q0.y * f0.y + q0.z * f1.x + q0.w * f1.y
                    + q1.x * f2.x + q1.y * f2.y + q1.z * f3.x + q1.w * f3.y;
            p += __shfl_down_sync(0xffffffffu, p, 4);
            p += __shfl_down_sync(0xffffffffu, p, 2);
            p += __shfl_down_sync(0xffffffffu, p, 1);
            if ((lane & 7) == 0) sc[head * 64 + m] = p;
        }
    }
    __syncthreads();

    // softmax
    if (tid < 128) {
        const int h = tid >> 5, l = tid & 31;
        float v0 = sc[h * 64 + l];
        float v1 = sc[h * 64 + 32 + l];
        float mx = fmaxf(v0, v1);
#pragma unroll
        for (int off = 16; off > 0; off >>= 1)
            mx = fmaxf(mx, __shfl_xor_sync(0xffffffffu, mx, off));
        float e0 = __expf(v0 - mx);
        float e1 = __expf(v1 - mx);
        float sum = e0 + e1;
#pragma unroll
        for (int off = 16; off > 0; off >>= 1)
            sum += __shfl_xor_sync(0xffffffffu, sum, off);
        float inv = 1.0f / sum;
        sc[h * 64 + l] = e0 * inv;
        sc[h * 64 + 32 + l] = e1 * inv;
    }
    __syncthreads();

    // out (fp16 store)
    {
        const int h = tid >> 6;
        const __half* vp = V + (size_t)st * HID + tid;
        const float* ap = &sc[h * 64];
        float o = 0.0f;
        int m = 0;
        for (; m + 4 <= len; m += 4) {
            float a0 = ap[m], a1 = ap[m + 1], a2 = ap[m + 2], a3 = ap[m + 3];
            float v0 = __half2float(vp[(size_t)m * HID]);
            float v1 = __half2float(vp[(size_t)(m + 1) * HID]);
            float v2 = __half2float(vp[(size_t)(m + 2) * HID]);
            float v3 = __half2float(vp[(size_t)(m + 3) * HID]);
            o = fmaf(a0, v0, o); o = fmaf(a1, v1, o);
            o = fmaf(a2, v2, o); o = fmaf(a3, v3, o);
        }
        for (; m < len; m++) o = fmaf(ap[m], __half2float(vp[(size_t)m * HID]), o);
        O[(size_t)b * HID + tid] = __float2half(o);
    }
}

// ======================= launch =======================
extern "C" void kernel_launch(void* const* d_in, const int* in_sizes, int n_in,
                              void* d_out, int out_size)
{
    const float* enc = (const float*)d_in[0];
    const float* soc = (const float*)d_in[1];
    const float* Wq = (const float*)d_in[2];
    const float* bq = (const float*)d_in[3];
    const float* Wk = (const float*)d_in[4];
    const float* bk = (const float*)d_in[5];
    const float* Wv = (const float*)d_in[6];
    const float* bv = (const float*)d_in[7];
    const float* Wf = (const float*)d_in[8];
    const float* bf = (const float*)d_in[9];
    const int* st = (const int*)d_in[10];
    const int* en = (const int*)d_in[11];
    float* out = (float*)d_out;

    float* qp;
    __half *kp, *vp, *op;
    cudaGetSymbolAddress((void**)&qp, g_Q);
    cudaGetSymbolAddress((void**)&kp, g_K);
    cudaGetSymbolAddress((void**)&vp, g_V);
    cudaGetSymbolAddress((void**)&op, g_O);

    cudaFuncSetAttribute(kvq_mma, cudaFuncAttributeMaxDynamicSharedMemorySize, KV_SMEM);
    cudaFuncSetAttribute(fin_mma, cudaFuncAttributeMaxDynamicSharedMemorySize, KV_SMEM);

    // weights -> fp16 (once)
    w2h<<<HID * HID / 256, 256>>>(Wk, Wv, Wq, Wf);
    // fused K,V,Q projections
    kvq_mma<<<NTOT / 128 + NB / 128, 256, KV_SMEM>>>(
        soc, enc, bk, bv, bq, kp, vp, qp);
    // attention (fp16 O out)
    attn3<<<NB, 256>>>(qp, kp, vp, st, en, op);
    // final projection via fp16 mma
    fin_mma<<<NB / 128, 256, KV_SMEM>>>(op, bf, out);
}

// round 10
// speedup vs baseline: 5.4201x; 1.0102x over previous
#include <cuda_runtime.h>
#include <cuda_fp16.h>
#include <cstdint>

#define HID 256
#define NB 4096
#define NTOT 131072

// Scratch (allocation-free rule: __device__ globals)
__device__ float  g_Q[(size_t)NB * HID];
__device__ __half g_K[(size_t)NTOT * HID];
__device__ __half g_V[(size_t)NTOT * HID];
__device__ __half g_O[(size_t)NB * HID];
__device__ __half g_Wk16[HID * HID];
__device__ __half g_Wv16[HID * HID];
__device__ __half g_Wq16[HID * HID];
__device__ __half g_Wf16[HID * HID];

// ======================= helpers =======================
__device__ __forceinline__ void mma_f16(float* d, const uint32_t* a, const uint32_t* b) {
    asm volatile(
        "mma.sync.aligned.m16n8k16.row.col.f32.f16.f16.f32 "
        "{%0,%1,%2,%3},{%4,%5,%6,%7},{%8,%9},{%0,%1,%2,%3};"
        : "+f"(d[0]), "+f"(d[1]), "+f"(d[2]), "+f"(d[3])
        : "r"(a[0]), "r"(a[1]), "r"(a[2]), "r"(a[3]), "r"(b[0]), "r"(b[1]));
}
__device__ __forceinline__ uint32_t h2u(float lo, float hi) {
    __half2 h = __floats2half2_rn(lo, hi);
    return *(uint32_t*)&h;
}
__device__ __forceinline__ uint32_t smem_u32(const void* p) {
    return (uint32_t)__cvta_generic_to_shared(p);
}
__device__ __forceinline__ void ldsm_x4(uint32_t& r0, uint32_t& r1, uint32_t& r2, uint32_t& r3,
                                        uint32_t addr) {
    asm volatile("ldmatrix.sync.aligned.m8n8.x4.shared.b16 {%0,%1,%2,%3}, [%4];"
                 : "=r"(r0), "=r"(r1), "=r"(r2), "=r"(r3) : "r"(addr));
}
__device__ __forceinline__ void cpa16(uint32_t dst, const void* src) {
    asm volatile("cp.async.ca.shared.global [%0], [%1], 16;" :: "r"(dst), "l"(src));
}
__device__ __forceinline__ void cpa_commit() {
    asm volatile("cp.async.commit_group;" ::: "memory");
}
__device__ __forceinline__ void cpa_wait2() {
    asm volatile("cp.async.wait_group 2;" ::: "memory");
}

#define AST2 132
#define BST2 20
#define BBUF (128 * BST2)                       // words per B ring slot
#define KV_SMEM ((128 * AST2 + 4 * BBUF) * 4)   // 108,544 B
#define FIN_SMEM ((32 * AST2 + 4 * BBUF) * 4)   // 57,856 B

// ======== weight fp32 -> fp16 pre-conversion (once per launch) ========
__global__ void __launch_bounds__(256) w2h(
    const float* __restrict__ Wk, const float* __restrict__ Wv,
    const float* __restrict__ Wq, const float* __restrict__ Wf)
{
    const int i = blockIdx.x * 256 + threadIdx.x;   // 0..65535
    g_Wk16[i] = __float2half_rn(Wk[i]);
    g_Wv16[i] = __float2half_rn(Wv[i]);
    g_Wq16[i] = __float2half_rn(Wq[i]);
    g_Wf16[i] = __float2half_rn(Wf[i]);
}

// issue one B chunk (128 n-rows x 32 k, fp16) via cp.async into ring slot
__device__ __forceinline__ void issue_b(const __half* W16, int nh, int kc,
                                        uint32_t bufb32, int tid) {
#pragma unroll
    for (int r = 0; r < 2; r++) {
        const int task = tid + r * 256;       // 0..511
        const int n = task >> 2;
        const int s = task & 3;               // 16B segment within 64B row
        cpa16(bufb32 + (uint32_t)((n * BST2 + s * 4) * 4),
              W16 + (size_t)(nh * 128 + n) * HID + kc * 32 + s * 8);
    }
}

// ============ fused K+V+Q projections (mma.sync fp16, 2-ahead cp.async) ============
// Blocks 0..1023: KV mode (A = soc, 4 passes: Wk-lo, Wk-hi, Wv-lo, Wv-hi -> fp16).
// Blocks 1024..1055: Q mode (A = enc, 2 passes over Wq, relu/16 -> fp32).
__global__ void __launch_bounds__(256, 2)
kvq_mma(const float* __restrict__ soc, const float* __restrict__ enc,
        const float* __restrict__ bk, const float* __restrict__ bv,
        const float* __restrict__ bq,
        __half* __restrict__ Kout, __half* __restrict__ Vout,
        float* __restrict__ Qout)
{
    extern __shared__ uint32_t sm32[];
    uint32_t* As = sm32;                  // 128 * 132 half2 words
    const uint32_t Abase = smem_u32(As);
    const uint32_t Bbase = Abase + 128 * AST2 * 4;   // 4 ring slots

    const int tid = threadIdx.x;
    const int lane = tid & 31;
    const int wid = tid >> 5;
    const int wm = wid & 1;               // m half (64 rows)
    const int wn = wid >> 1;              // n quarter (32 cols)
    const int bm = blockIdx.x;
    const bool isQ = (bm >= NTOT / 128);
    const int rowblk = isQ ? (bm - NTOT / 128) : bm;
    const int ntc_total = isQ ? 16 : 32;

    // LDSM lane address components
    const int arow = wm * 64 + (lane & 15);
    const int acol = (lane >> 4) << 2;
    const int brow = wn * 32 + ((lane >> 4) << 3) + (lane & 7);
    const int bcol = ((lane >> 3) & 1) << 2;

    // ---- issue B chunks 0 and 1 ----
    const __half* WK16 = isQ ? g_Wq16 : g_Wk16;
    const __half* WV16 = isQ ? g_Wq16 : g_Wv16;
    issue_b(WK16, 0, 0, Bbase, tid);
    cpa_commit();
    issue_b(WK16, 0, 1, Bbase + BBUF * 4, tid);
    cpa_commit();

    // ---- stage A tile 128x256 -> fp16 (overlaps with cp.async above) ----
    const float* Ab = (isQ ? enc : soc) + (size_t)rowblk * 128 * HID;
#pragma unroll
    for (int i = 0; i < 32; i++) {
        int idx = i * 256 + tid;
        int r = idx >> 6, c4 = (idx & 63) << 2;
        float4 v = *(const float4*)(Ab + (size_t)r * HID + c4);
        uint2 h;
        h.x = h2u(v.x, v.y);
        h.y = h2u(v.z, v.w);
        *(uint2*)&As[r * AST2 + (c4 >> 1)] = h;
    }
    __syncthreads();   // A staged & visible: A-frag LDSMs may precede chunk barriers

    float acc[4][4][4];
#pragma unroll
    for (int i = 0; i < 4; i++)
#pragma unroll
        for (int j = 0; j < 4; j++)
#pragma unroll
            for (int t = 0; t < 4; t++) acc[i][j][t] = 0.0f;

    for (int tc = 0; tc < ntc_total; tc++) {
        const int p = tc >> 3;            // pass
        const int kc = tc & 7;            // k chunk (32 k each)

        // hoisted A frags for ks=0 (A immutable; no barrier needed)
        uint32_t a0[4][4];
        {
            const int kb = kc * 16;
#pragma unroll
            for (int i = 0; i < 4; i++)
                ldsm_x4(a0[i][0], a0[i][1], a0[i][2], a0[i][3],
                        Abase + (uint32_t)(((arow + i * 16) * AST2 + kb + acol) * 4));
        }

        // issue chunk tc+2 into ring slot (tc+2)&3
        if (tc + 2 < ntc_total) {
            const int ntc = tc + 2;
            const int np = ntc >> 3, nkc = ntc & 7;
            const __half* W = (np < 2) ? WK16 : WV16;
            issue_b(W, np & 1, nkc, Bbase + (uint32_t)(((ntc) & 3) * BBUF * 4), tid);
        }
        cpa_commit();
        cpa_wait2();          // chunk tc complete; tc+1, tc+2 may be in flight
        __syncthreads();

        const uint32_t Bb32 = Bbase + (uint32_t)((tc & 3) * BBUF * 4);

        // ks = 0 (A frags already in registers)
        {
            uint32_t b[4][2];
            const int bk0 = bcol;
            ldsm_x4(b[0][0], b[0][1], b[1][0], b[1][1],
                    Bb32 + (uint32_t)((brow * BST2 + bk0) * 4));
            ldsm_x4(b[2][0], b[2][1], b[3][0], b[3][1],
                    Bb32 + (uint32_t)(((brow + 16) * BST2 + bk0) * 4));
#pragma unroll
            for (int i = 0; i < 4; i++)
#pragma unroll
                for (int j = 0; j < 4; j++) mma_f16(acc[i][j], a0[i], b[j]);
        }
        // ks = 1
        {
            const int kb = kc * 16 + 8;
            uint32_t a[4][4];
#pragma unroll
            for (int i = 0; i < 4; i++)
                ldsm_x4(a[i][0], a[i][1], a[i][2], a[i][3],
                        Abase + (uint32_t)(((arow + i * 16) * AST2 + kb + acol) * 4));
            uint32_t b[4][2];
            const int bk0 = 8 + bcol;
            ldsm_x4(b[0][0], b[0][1], b[1][0], b[1][1],
                    Bb32 + (uint32_t)((brow * BST2 + bk0) * 4));
            ldsm_x4(b[2][0], b[2][1], b[3][0], b[3][1],
                    Bb32 + (uint32_t)(((brow + 16) * BST2 + bk0) * 4));
#pragma unroll
            for (int i = 0; i < 4; i++)
#pragma unroll
                for (int j = 0; j < 4; j++) mma_f16(acc[i][j], a[i], b[j]);
        }

        // end of a pass -> epilogue + reset accum
        if (kc == 7) {
            const int nh = p & 1;
            const int colw = nh * 128 + wn * 32 + (lane & 3) * 2;
            const size_t rowb = (size_t)rowblk * 128 + wm * 64 + (lane >> 2);
            if (isQ) {
#pragma unroll
                for (int j = 0; j < 4; j++) {
                    const float2 bb = *(const float2*)&bq[colw + j * 8];
#pragma unroll
                    for (int i = 0; i < 4; i++) {
                        const size_t r0 = rowb + i * 16;
                        float2 o0, o1;
                        o0.x = fmaxf(acc[i][j][0] + bb.x, 0.0f) * 0.0625f;
                        o0.y = fmaxf(acc[i][j][1] + bb.y, 0.0f) * 0.0625f;
                        o1.x = fmaxf(acc[i][j][2] + bb.x, 0.0f) * 0.0625f;
                        o1.y = fmaxf(acc[i][j][3] + bb.y, 0.0f) * 0.0625f;
                        *(float2*)&Qout[r0 * HID + colw + j * 8] = o0;
                        *(float2*)&Qout[(r0 + 8) * HID + colw + j * 8] = o1;
#pragma unroll
                        for (int t = 0; t < 4; t++) acc[i][j][t] = 0.0f;
                    }
                }
            } else {
                const float* bias = (p < 2) ? bk : bv;
                __half* Cout = (p < 2) ? Kout : Vout;
#pragma unroll
                for (int j = 0; j < 4; j++) {
                    const float2 bb = *(const float2*)&bias[colw + j * 8];
#pragma unroll
                    for (int i = 0; i < 4; i++) {
                        const size_t r0 = rowb + i * 16;
                        uint32_t u0 = h2u(fmaxf(acc[i][j][0] + bb.x, 0.0f),
                                          fmaxf(acc[i][j][1] + bb.y, 0.0f));
                        uint32_t u1 = h2u(fmaxf(acc[i][j][2] + bb.x, 0.0f),
                                          fmaxf(acc[i][j][3] + bb.y, 0.0f));
                        *(uint32_t*)&Cout[r0 * HID + colw + j * 8] = u0;
                        *(uint32_t*)&Cout[(r0 + 8) * HID + colw + j * 8] = u1;
#pragma unroll
                        for (int t = 0; t < 4; t++) acc[i][j][t] = 0.0f;
                    }
                }
            }
        }
    }
}

// ============ final projection: 32-row tiles, 128 CTAs (mma.sync fp16) ============
__global__ void __launch_bounds__(256, 2)
fin_mma(const __half* __restrict__ O, const float* __restrict__ bf,
        float* __restrict__ out)
{
    extern __shared__ uint32_t sm32[];
    uint32_t* As = sm32;                  // 32 * 132 half2 words
    const uint32_t Abase = smem_u32(As);
    const uint32_t Bbase = Abase + 32 * AST2 * 4;

    const int tid = threadIdx.x;
    const int lane = tid & 31;
    const int wid = tid >> 5;
    const int wm = wid & 1;               // 16-row half
    const int wn = wid >> 1;              // 32-col quarter
    const int bm = blockIdx.x;

    const int arow = wm * 16 + (lane & 15);
    const int acol = (lane >> 4) << 2;
    const int brow = wn * 32 + ((lane >> 4) << 3) + (lane & 7);
    const int bcol = ((lane >> 3) & 1) << 2;

    issue_b(g_Wf16, 0, 0, Bbase, tid);
    cpa_commit();
    issue_b(g_Wf16, 0, 1, Bbase + BBUF * 4, tid);
    cpa_commit();

    // ---- stage A tile 32x256 (already fp16) ----
    const __half* Ab = O + (size_t)bm * 32 * HID;
#pragma unroll
    for (int i = 0; i < 4; i++) {
        int idx = i * 256 + tid;
        int r = idx >> 5, c2 = (idx & 31) * 4;
        uint4 v = *(const uint4*)(Ab + (size_t)r * HID + c2 * 2);
        *(uint4*)&As[r * AST2 + c2] = v;
    }
    __syncthreads();

    float acc[4][4];
#pragma unroll
    for (int j = 0; j < 4; j++)
#pragma unroll
        for (int t = 0; t < 4; t++) acc[j][t] = 0.0f;

    for (int tc = 0; tc < 16; tc++) {
        const int p = tc >> 3;
        const int kc = tc & 7;

        uint32_t a0[4];
        ldsm_x4(a0[0], a0[1], a0[2], a0[3],
                Abase + (uint32_t)((arow * AST2 + kc * 16 + acol) * 4));

        if (tc + 2 < 16) {
            const int ntc = tc + 2;
            issue_b(g_Wf16, (ntc >> 3) & 1, ntc & 7,
                    Bbase + (uint32_t)((ntc & 3) * BBUF * 4), tid);
        }
        cpa_commit();
        cpa_wait2();
        __syncthreads();

        const uint32_t Bb32 = Bbase + (uint32_t)((tc & 3) * BBUF * 4);
        {
            uint32_t b[4][2];
            ldsm_x4(b[0][0], b[0][1], b[1][0], b[1][1],
                    Bb32 + (uint32_t)((brow * BST2 + bcol) * 4));
            ldsm_x4(b[2][0], b[2][1], b[3][0], b[3][1],
                    Bb32 + (uint32_t)(((brow + 16) * BST2 + bcol) * 4));
#pragma unroll
            for (int j = 0; j < 4; j++) mma_f16(acc[j], a0, b[j]);
        }
        {
            uint32_t a[4];
            ldsm_x4(a[0], a[1], a[2], a[3],
                    Abase + (uint32_t)((arow * AST2 + kc * 16 + 8 + acol) * 4));
            uint32_t b[4][2];
            const int bk0 = 8 + bcol;
            ldsm_x4(b[0][0], b[0][1], b[1][0], b[1][1],
                    Bb32 + (uint32_t)((brow * BST2 + bk0) * 4));
            ldsm_x4(b[2][0], b[2][1], b[3][0], b[3][1],
                    Bb32 + (uint32_t)(((brow + 16) * BST2 + bk0) * 4));
#pragma unroll
            for (int j = 0; j < 4; j++) mma_f16(acc[j], a, b[j]);
        }

        if (kc == 7) {
            const int nh = p & 1;
            const int colw = nh * 128 + wn * 32 + (lane & 3) * 2;
            const size_t rowb = (size_t)bm * 32 + wm * 16 + (lane >> 2);
#pragma unroll
            for (int j = 0; j < 4; j++) {
                const float2 bb = *(const float2*)&bf[colw + j * 8];
                float2 o0, o1;
                o0.x = acc[j][0] + bb.x;
                o0.y = acc[j][1] + bb.y;
                o1.x = acc[j][2] + bb.x;
                o1.y = acc[j][3] + bb.y;
                *(float2*)&out[rowb * HID + colw + j * 8] = o0;
                *(float2*)&out[(rowb + 8) * HID + colw + j * 8] = o1;
#pragma unroll
                for (int t = 0; t < 4; t++) acc[j][t] = 0.0f;
            }
        }
    }
}

// ======================= attention: 1 CTA / sample, fp16 K/V, fp16 O ==============
__global__ __launch_bounds__(256) void attn3(
    const float* __restrict__ Q, const __half* __restrict__ K,
    const __half* __restrict__ V, const int* __restrict__ starts,
    const int* __restrict__ ends, __half* __restrict__ O)
{
    __shared__ float qs[256];
    __shared__ float sc[256];

    const int tid = threadIdx.x;
    const int lane = tid & 31;
    const int wid = tid >> 5;
    const int b = blockIdx.x;
    const int st = starts[b];
    const int len = ends[b] - st;     // 1..64

    qs[tid] = Q[(size_t)b * HID + tid];
    sc[tid] = -1e30f;
    __syncthreads();

    float4 q0 = *(const float4*)&qs[lane * 8];
    float4 q1 = *(const float4*)&qs[lane * 8 + 4];
    const int head = lane >> 3;

    // scores
#pragma unroll
    for (int rr = 0; rr < 8; rr++) {
        const int m = rr * 8 + wid;
        if (m < len) {
            uint4 raw = *(const uint4*)(K + (size_t)(st + m) * HID + lane * 8);
            float2 f0 = __half22float2(*(__half2*)&raw.x);
            float2 f1 = __half22float2(*(__half2*)&raw.y);
            float2 f2 = __half22float2(*(__half2*)&raw.z);
            float2 f3 = __half22float2(*(__half2*)&raw.w);
            float p = q0.x * f0.x + q0.y * f0.y + q0.z * f1.x + q0.w * f1.y
                    + q1.x * f2.x + q1.y * f2.y + q1.z * f3.x + q1.w * f3.y;
            p += __shfl_down_sync(0xffffffffu, p, 4);
            p += __shfl_down_sync(0xffffffffu, p, 2);
            p += __shfl_down_sync(0xffffffffu, p, 1);
            if ((lane & 7) == 0) sc[head * 64 + m] = p;
        }
    }
    __syncthreads();

    // softmax
    if (tid < 128) {
        const int h = tid >> 5, l = tid & 31;
        float v0 = sc[h * 64 + l];
        float v1 = sc[h * 64 + 32 + l];
        float mx = fmaxf(v0, v1);
#pragma unroll
        for (int off = 16; off > 0; off >>= 1)
            mx = fmaxf(mx, __shfl_xor_sync(0xffffffffu, mx, off));
        float e0 = __expf(v0 - mx);
        float e1 = __expf(v1 - mx);
        float sum = e0 + e1;
#pragma unroll
        for (int off = 16; off > 0; off >>= 1)
            sum += __shfl_xor_sync(0xffffffffu, sum, off);
        float inv = 1.0f / sum;
        sc[h * 64 + l] = e0 * inv;
        sc[h * 64 + 32 + l] = e1 * inv;
    }
    __syncthreads();

    // out (fp16 store)
    {
        const int h = tid >> 6;
        const __half* vp = V + (size_t)st * HID + tid;
        const float* ap = &sc[h * 64];
        float o = 0.0f;
        int m = 0;
        for (; m + 4 <= len; m += 4) {
            float a0 = ap[m], a1 = ap[m + 1], a2 = ap[m + 2], a3 = ap[m + 3];
            float v0 = __half2float(vp[(size_t)m * HID]);
            float v1 = __half2float(vp[(size_t)(m + 1) * HID]);
            float v2 = __half2float(vp[(size_t)(m + 2) * HID]);
            float v3 = __half2float(vp[(size_t)(m + 3) * HID]);
            o = fmaf(a0, v0, o); o = fmaf(a1, v1, o);
            o = fmaf(a2, v2, o); o = fmaf(a3, v3, o);
        }
        for (; m < len; m++) o = fmaf(ap[m], __half2float(vp[(size_t)m * HID]), o);
        O[(size_t)b * HID + tid] = __float2half(o);
    }
}

// ======================= launch =======================
extern "C" void kernel_launch(void* const* d_in, const int* in_sizes, int n_in,
                              void* d_out, int out_size)
{
    const float* enc = (const float*)d_in[0];
    const float* soc = (const float*)d_in[1];
    const float* Wq = (const float*)d_in[2];
    const float* bq = (const float*)d_in[3];
    const float* Wk = (const float*)d_in[4];
    const float* bk = (const float*)d_in[5];
    const float* Wv = (const float*)d_in[6];
    const float* bv = (const float*)d_in[7];
    const float* Wf = (const float*)d_in[8];
    const float* bf = (const float*)d_in[9];
    const int* st = (const int*)d_in[10];
    const int* en = (const int*)d_in[11];
    float* out = (float*)d_out;

    float* qp;
    __half *kp, *vp, *op;
    cudaGetSymbolAddress((void**)&qp, g_Q);
    cudaGetSymbolAddress((void**)&kp, g_K);
    cudaGetSymbolAddress((void**)&vp, g_V);
    cudaGetSymbolAddress((void**)&op, g_O);

    cudaFuncSetAttribute(kvq_mma, cudaFuncAttributeMaxDynamicSharedMemorySize, KV_SMEM);
    cudaFuncSetAttribute(fin_mma, cudaFuncAttributeMaxDynamicSharedMemorySize, FIN_SMEM);

    // weights -> fp16 (once)
    w2h<<<HID * HID / 256, 256>>>(Wk, Wv, Wq, Wf);
    // fused K,V,Q projections
    kvq_mma<<<NTOT / 128 + NB / 128, 256, KV_SMEM>>>(
        soc, enc, bk, bv, bq, kp, vp, qp);
    // attention (fp16 O out)
    attn3<<<NB, 256>>>(qp, kp, vp, st, en, op);
    // final projection via fp16 mma (32-row tiles)
    fin_mma<<<NB / 32, 256, FIN_SMEM>>>(op, bf, out);
}

// round 11
// speedup vs baseline: 6.4097x; 1.1826x over previous
#include <cuda_runtime.h>
#include <cuda_fp16.h>
#include <cstdint>

#define HID 256
#define NB 4096
#define NTOT 131072

// Scratch (allocation-free rule: __device__ globals)
__device__ float  g_Q[(size_t)NB * HID];
__device__ __half g_K[(size_t)NTOT * HID];
__device__ __half g_V[(size_t)NTOT * HID];
__device__ __half g_O[(size_t)NB * HID];
__device__ __half g_Wk16[HID * HID];
__device__ __half g_Wv16[HID * HID];
__device__ __half g_Wq16[HID * HID];
__device__ __half g_Wf16[HID * HID];
__device__ int    g_idx[NTOT];
__device__ unsigned char g_flag[NTOT];
__device__ int    g_count;

// ======================= helpers =======================
__device__ __forceinline__ void mma_f16(float* d, const uint32_t* a, const uint32_t* b) {
    asm volatile(
        "mma.sync.aligned.m16n8k16.row.col.f32.f16.f16.f32 "
        "{%0,%1,%2,%3},{%4,%5,%6,%7},{%8,%9},{%0,%1,%2,%3};"
        : "+f"(d[0]), "+f"(d[1]), "+f"(d[2]), "+f"(d[3])
        : "r"(a[0]), "r"(a[1]), "r"(a[2]), "r"(a[3]), "r"(b[0]), "r"(b[1]));
}
__device__ __forceinline__ uint32_t h2u(float lo, float hi) {
    __half2 h = __floats2half2_rn(lo, hi);
    return *(uint32_t*)&h;
}
__device__ __forceinline__ uint32_t smem_u32(const void* p) {
    return (uint32_t)__cvta_generic_to_shared(p);
}
__device__ __forceinline__ void ldsm_x4(uint32_t& r0, uint32_t& r1, uint32_t& r2, uint32_t& r3,
                                        uint32_t addr) {
    asm volatile("ldmatrix.sync.aligned.m8n8.x4.shared.b16 {%0,%1,%2,%3}, [%4];"
                 : "=r"(r0), "=r"(r1), "=r"(r2), "=r"(r3) : "r"(addr));
}
__device__ __forceinline__ void cpa16(uint32_t dst, const void* src) {
    asm volatile("cp.async.ca.shared.global [%0], [%1], 16;" :: "r"(dst), "l"(src));
}
__device__ __forceinline__ void cpa_commit() {
    asm volatile("cp.async.commit_group;" ::: "memory");
}
__device__ __forceinline__ void cpa_wait2() {
    asm volatile("cp.async.wait_group 2;" ::: "memory");
}

#define AST2 132
#define BST2 20
#define BBUF (128 * BST2)
#define KV_SMEM ((128 * AST2 + 4 * BBUF) * 4)
#define FIN_SMEM ((32 * AST2 + 4 * BBUF) * 4)

// ======== prep kernels ========
__global__ void __launch_bounds__(256) zerofill() {
    const int i = blockIdx.x * 256 + threadIdx.x;    // grid 512 -> 131072
    g_idx[i] = 0;
    if (i < NTOT / 4) ((int*)g_flag)[i] = 0;
    if (i == 0) g_count = 0;
}

__global__ void __launch_bounds__(256) mark(const int* __restrict__ st,
                                            const int* __restrict__ en) {
    const int w = (blockIdx.x * 256 + threadIdx.x) >> 5;   // grid 128 -> 1024 warps
    const int lane = threadIdx.x & 31;
#pragma unroll
    for (int q = 0; q < 4; q++) {
        const int s = w * 4 + q;                 // 0..4095
        const int a = st[s], b = en[s];
        for (int r = a + lane; r < b; r += 32) g_flag[r] = 1;
    }
}

__global__ void __launch_bounds__(256) compact() {
    const int i = blockIdx.x * 256 + threadIdx.x;    // grid 512
    const int lane = threadIdx.x & 31;
    const int f = g_flag[i];
    const unsigned mask = __ballot_sync(0xffffffffu, f);
    int base = 0;
    if (lane == 0 && mask) base = atomicAdd(&g_count, __popc(mask));
    base = __shfl_sync(0xffffffffu, base, 0);
    if (f) g_idx[base + __popc(mask & ((1u << lane) - 1u))] = i;
}

// ======== weight fp32 -> fp16 pre-conversion ========
__global__ void __launch_bounds__(256) w2h(
    const float* __restrict__ Wk, const float* __restrict__ Wv,
    const float* __restrict__ Wq, const float* __restrict__ Wf)
{
    const int i = blockIdx.x * 256 + threadIdx.x;
    g_Wk16[i] = __float2half_rn(Wk[i]);
    g_Wv16[i] = __float2half_rn(Wv[i]);
    g_Wq16[i] = __float2half_rn(Wq[i]);
    g_Wf16[i] = __float2half_rn(Wf[i]);
}

// issue one B chunk (128 n-rows x 32 k, fp16) via cp.async into ring slot
__device__ __forceinline__ void issue_b(const __half* W16, int nh, int kc,
                                        uint32_t bufb32, int tid) {
#pragma unroll
    for (int r = 0; r < 2; r++) {
        const int task = tid + r * 256;
        const int n = task >> 2;
        const int s = task & 3;
        cpa16(bufb32 + (uint32_t)((n * BST2 + s * 4) * 4),
              W16 + (size_t)(nh * 128 + n) * HID + kc * 32 + s * 8);
    }
}

// ============ fused K+V+Q projections: gather-GEMM over covered rows ============
// Blocks 0..1023: KV mode on compacted rows g_idx[bm*128 ..]; exit if beyond count.
// Blocks 1024..1055: Q mode (A = enc, 2 passes over Wq, relu/16 -> fp32).
__global__ void __launch_bounds__(256, 2)
kvq_mma(const float* __restrict__ soc, const float* __restrict__ enc,
        const float* __restrict__ bk, const float* __restrict__ bv,
        const float* __restrict__ bq,
        __half* __restrict__ Kout, __half* __restrict__ Vout,
        float* __restrict__ Qout)
{
    extern __shared__ uint32_t sm32[];
    uint32_t* As = sm32;
    const uint32_t Abase = smem_u32(As);
    const uint32_t Bbase = Abase + 128 * AST2 * 4;

    const int tid = threadIdx.x;
    const int lane = tid & 31;
    const int wid = tid >> 5;
    const int wm = wid & 1;
    const int wn = wid >> 1;
    const int bm = blockIdx.x;
    const bool isQ = (bm >= NTOT / 128);
    const int rowblk = isQ ? (bm - NTOT / 128) : bm;
    const int ntc_total = isQ ? 16 : 32;
    const int gbase = rowblk * 128;

    if (!isQ && gbase >= g_count) return;    // dead block: rows not covered

    const int arow = wm * 64 + (lane & 15);
    const int acol = (lane >> 4) << 2;
    const int brow = wn * 32 + ((lane >> 4) << 3) + (lane & 7);
    const int bcol = ((lane >> 3) & 1) << 2;

    const __half* WK16 = isQ ? g_Wq16 : g_Wk16;
    const __half* WV16 = isQ ? g_Wq16 : g_Wv16;
    issue_b(WK16, 0, 0, Bbase, tid);
    cpa_commit();
    issue_b(WK16, 0, 1, Bbase + BBUF * 4, tid);
    cpa_commit();

    // ---- stage A tile 128x256 -> fp16 (gathered rows for KV mode) ----
#pragma unroll
    for (int i = 0; i < 32; i++) {
        int idx = i * 256 + tid;
        int r = idx >> 6, c4 = (idx & 63) << 2;
        const size_t grow = isQ ? (size_t)(gbase + r) : (size_t)g_idx[gbase + r];
        const float* src = (isQ ? enc : soc) + grow * HID + c4;
        float4 v = *(const float4*)src;
        uint2 h;
        h.x = h2u(v.x, v.y);
        h.y = h2u(v.z, v.w);
        *(uint2*)&As[r * AST2 + (c4 >> 1)] = h;
    }
    __syncthreads();

    float acc[4][4][4];
#pragma unroll
    for (int i = 0; i < 4; i++)
#pragma unroll
        for (int j = 0; j < 4; j++)
#pragma unroll
            for (int t = 0; t < 4; t++) acc[i][j][t] = 0.0f;

    for (int tc = 0; tc < ntc_total; tc++) {
        const int p = tc >> 3;
        const int kc = tc & 7;

        // hoisted A frags for ks=0 (A immutable)
        uint32_t a0[4][4];
        {
            const int kb = kc * 16;
#pragma unroll
            for (int i = 0; i < 4; i++)
                ldsm_x4(a0[i][0], a0[i][1], a0[i][2], a0[i][3],
                        Abase + (uint32_t)(((arow + i * 16) * AST2 + kb + acol) * 4));
        }

        if (tc + 2 < ntc_total) {
            const int ntc = tc + 2;
            const int np = ntc >> 3, nkc = ntc & 7;
            const __half* W = (np < 2) ? WK16 : WV16;
            issue_b(W, np & 1, nkc, Bbase + (uint32_t)(((ntc) & 3) * BBUF * 4), tid);
        }
        cpa_commit();
        cpa_wait2();
        __syncthreads();

        const uint32_t Bb32 = Bbase + (uint32_t)((tc & 3) * BBUF * 4);

        // ks = 0
        {
            uint32_t b[4][2];
            ldsm_x4(b[0][0], b[0][1], b[1][0], b[1][1],
                    Bb32 + (uint32_t)((brow * BST2 + bcol) * 4));
            ldsm_x4(b[2][0], b[2][1], b[3][0], b[3][1],
                    Bb32 + (uint32_t)(((brow + 16) * BST2 + bcol) * 4));
#pragma unroll
            for (int i = 0; i < 4; i++)
#pragma unroll
                for (int j = 0; j < 4; j++) mma_f16(acc[i][j], a0[i], b[j]);
        }
        // ks = 1
        {
            const int kb = kc * 16 + 8;
            uint32_t a[4][4];
#pragma unroll
            for (int i = 0; i < 4; i++)
                ldsm_x4(a[i][0], a[i][1], a[i][2], a[i][3],
                        Abase + (uint32_t)(((arow + i * 16) * AST2 + kb + acol) * 4));
            uint32_t b[4][2];
            const int bk0 = 8 + bcol;
            ldsm_x4(b[0][0], b[0][1], b[1][0], b[1][1],
                    Bb32 + (uint32_t)((brow * BST2 + bk0) * 4));
            ldsm_x4(b[2][0], b[2][1], b[3][0], b[3][1],
                    Bb32 + (uint32_t)(((brow + 16) * BST2 + bk0) * 4));
#pragma unroll
            for (int i = 0; i < 4; i++)
#pragma unroll
                for (int j = 0; j < 4; j++) mma_f16(acc[i][j], a[i], b[j]);
        }

        // end of a pass -> epilogue (scatter for KV) + reset accum
        if (kc == 7) {
            const int nh = p & 1;
            const int colw = nh * 128 + wn * 32 + (lane & 3) * 2;
            const int lrow = wm * 64 + (lane >> 2);
            if (isQ) {
#pragma unroll
                for (int j = 0; j < 4; j++) {
                    const float2 bb = *(const float2*)&bq[colw + j * 8];
#pragma unroll
                    for (int i = 0; i < 4; i++) {
                        const size_t r0 = (size_t)gbase + lrow + i * 16;
                        float2 o0, o1;
                        o0.x = fmaxf(acc[i][j][0] + bb.x, 0.0f) * 0.0625f;
                        o0.y = fmaxf(acc[i][j][1] + bb.y, 0.0f) * 0.0625f;
                        o1.x = fmaxf(acc[i][j][2] + bb.x, 0.0f) * 0.0625f;
                        o1.y = fmaxf(acc[i][j][3] + bb.y, 0.0f) * 0.0625f;
                        *(float2*)&Qout[r0 * HID + colw + j * 8] = o0;
                        *(float2*)&Qout[(r0 + 8) * HID + colw + j * 8] = o1;
#pragma unroll
                        for (int t = 0; t < 4; t++) acc[i][j][t] = 0.0f;
                    }
                }
            } else {
                const float* bias = (p < 2) ? bk : bv;
                __half* Cout = (p < 2) ? Kout : Vout;
#pragma unroll
                for (int i = 0; i < 4; i++) {
                    const size_t r0 = (size_t)g_idx[gbase + lrow + i * 16];
                    const size_t r1 = (size_t)g_idx[gbase + lrow + i * 16 + 8];
#pragma unroll
                    for (int j = 0; j < 4; j++) {
                        const float2 bb = *(const float2*)&bias[colw + j * 8];
                        uint32_t u0 = h2u(fmaxf(acc[i][j][0] + bb.x, 0.0f),
                                          fmaxf(acc[i][j][1] + bb.y, 0.0f));
                        uint32_t u1 = h2u(fmaxf(acc[i][j][2] + bb.x, 0.0f),
                                          fmaxf(acc[i][j][3] + bb.y, 0.0f));
                        *(uint32_t*)&Cout[r0 * HID + colw + j * 8] = u0;
                        *(uint32_t*)&Cout[r1 * HID + colw + j * 8] = u1;
#pragma unroll
                        for (int t = 0; t < 4; t++) acc[i][j][t] = 0.0f;
                    }
                }
            }
        }
    }
}

// ============ final projection: 32-row tiles, 128 CTAs (mma.sync fp16) ============
__global__ void __launch_bounds__(256, 2)
fin_mma(const __half* __restrict__ O, const float* __restrict__ bf,
        float* __restrict__ out)
{
    extern __shared__ uint32_t sm32[];
    uint32_t* As = sm32;
    const uint32_t Abase = smem_u32(As);
    const uint32_t Bbase = Abase + 32 * AST2 * 4;

    const int tid = threadIdx.x;
    const int lane = tid & 31;
    const int wid = tid >> 5;
    const int wm = wid & 1;
    const int wn = wid >> 1;
    const int bm = blockIdx.x;

    const int arow = wm * 16 + (lane & 15);
    const int acol = (lane >> 4) << 2;
    const int brow = wn * 32 + ((lane >> 4) << 3) + (lane & 7);
    const int bcol = ((lane >> 3) & 1) << 2;

    issue_b(g_Wf16, 0, 0, Bbase, tid);
    cpa_commit();
    issue_b(g_Wf16, 0, 1, Bbase + BBUF * 4, tid);
    cpa_commit();

    const __half* Ab = O + (size_t)bm * 32 * HID;
#pragma unroll
    for (int i = 0; i < 4; i++) {
        int idx = i * 256 + tid;
        int r = idx >> 5, c2 = (idx & 31) * 4;
        uint4 v = *(const uint4*)(Ab + (size_t)r * HID + c2 * 2);
        *(uint4*)&As[r * AST2 + c2] = v;
    }
    __syncthreads();

    float acc[4][4];
#pragma unroll
    for (int j = 0; j < 4; j++)
#pragma unroll
        for (int t = 0; t < 4; t++) acc[j][t] = 0.0f;

    for (int tc = 0; tc < 16; tc++) {
        const int p = tc >> 3;
        const int kc = tc & 7;

        uint32_t a0[4];
        ldsm_x4(a0[0], a0[1], a0[2], a0[3],
                Abase + (uint32_t)((arow * AST2 + kc * 16 + acol) * 4));

        if (tc + 2 < 16) {
            const int ntc = tc + 2;
            issue_b(g_Wf16, (ntc >> 3) & 1, ntc & 7,
                    Bbase + (uint32_t)((ntc & 3) * BBUF * 4), tid);
        }
        cpa_commit();
        cpa_wait2();
        __syncthreads();

        const uint32_t Bb32 = Bbase + (uint32_t)((tc & 3) * BBUF * 4);
        {
            uint32_t b[4][2];
            ldsm_x4(b[0][0], b[0][1], b[1][0], b[1][1],
                    Bb32 + (uint32_t)((brow * BST2 + bcol) * 4));
            ldsm_x4(b[2][0], b[2][1], b[3][0], b[3][1],
                    Bb32 + (uint32_t)(((brow + 16) * BST2 + bcol) * 4));
#pragma unroll
            for (int j = 0; j < 4; j++) mma_f16(acc[j], a0, b[j]);
        }
        {
            uint32_t a[4];
            ldsm_x4(a[0], a[1], a[2], a[3],
                    Abase + (uint32_t)((arow * AST2 + kc * 16 + 8 + acol) * 4));
            uint32_t b[4][2];
            const int bk0 = 8 + bcol;
            ldsm_x4(b[0][0], b[0][1], b[1][0], b[1][1],
                    Bb32 + (uint32_t)((brow * BST2 + bk0) * 4));
            ldsm_x4(b[2][0], b[2][1], b[3][0], b[3][1],
                    Bb32 + (uint32_t)(((brow + 16) * BST2 + bk0) * 4));
#pragma unroll
            for (int j = 0; j < 4; j++) mma_f16(acc[j], a, b[j]);
        }

        if (kc == 7) {
            const int nh = p & 1;
            const int colw = nh * 128 + wn * 32 + (lane & 3) * 2;
            const size_t rowb = (size_t)bm * 32 + wm * 16 + (lane >> 2);
#pragma unroll
            for (int j = 0; j < 4; j++) {
                const float2 bb = *(const float2*)&bf[colw + j * 8];
                float2 o0, o1;
                o0.x = acc[j][0] + bb.x;
                o0.y = acc[j][1] + bb.y;
                o1.x = acc[j][2] + bb.x;
                o1.y = acc[j][3] + bb.y;
                *(float2*)&out[rowb * HID + colw + j * 8] = o0;
                *(float2*)&out[(rowb + 8) * HID + colw + j * 8] = o1;
#pragma unroll
                for (int t = 0; t < 4; t++) acc[j][t] = 0.0f;
            }
        }
    }
}

// ======================= attention: 1 CTA / sample, fp16 K/V, fp16 O ==============
__global__ __launch_bounds__(256) void attn3(
    const float* __restrict__ Q, const __half* __restrict__ K,
    const __half* __restrict__ V, const int* __restrict__ starts,
    const int* __restrict__ ends, __half* __restrict__ O)
{
    __shared__ float qs[256];
    __shared__ float sc[256];

    const int tid = threadIdx.x;
    const int lane = tid & 31;
    const int wid = tid >> 5;
    const int b = blockIdx.x;
    const int st = starts[b];
    const int len = ends[b] - st;

    qs[tid] = Q[(size_t)b * HID + tid];
    sc[tid] = -1e30f;
    __syncthreads();

    float4 q0 = *(const float4*)&qs[lane * 8];
    float4 q1 = *(const float4*)&qs[lane * 8 + 4];
    const int head = lane >> 3;

#pragma unroll
    for (int rr = 0; rr < 8; rr++) {
        const int m = rr * 8 + wid;
        if (m < len) {
            uint4 raw = *(const uint4*)(K + (size_t)(st + m) * HID + lane * 8);
            float2 f0 = __half22float2(*(__half2*)&raw.x);
            float2 f1 = __half22float2(*(__half2*)&raw.y);
            float2 f2 = __half22float2(*(__half2*)&raw.z);
            float2 f3 = __half22float2(*(__half2*)&raw.w);
            float p = q0.x * f0.x + q0.y * f0.y + q0.z * f1.x + q0.w * f1.y
                    + q1.x * f2.x + q1.y * f2.y + q1.z * f3.x + q1.w * f3.y;
            p += __shfl_down_sync(0xffffffffu, p, 4);
            p += __shfl_down_sync(0xffffffffu, p, 2);
            p += __shfl_down_sync(0xffffffffu, p, 1);
            if ((lane & 7) == 0) sc[head * 64 + m] = p;
        }
    }
    __syncthreads();

    if (tid < 128) {
        const int h = tid >> 5, l = tid & 31;
        float v0 = sc[h * 64 + l];
        float v1 = sc[h * 64 + 32 + l];
        float mx = fmaxf(v0, v1);
#pragma unroll
        for (int off = 16; off > 0; off >>= 1)
            mx = fmaxf(mx, __shfl_xor_sync(0xffffffffu, mx, off));
        float e0 = __expf(v0 - mx);
        float e1 = __expf(v1 - mx);
        float sum = e0 + e1;
#pragma unroll
        for (int off = 16; off > 0; off >>= 1)
            sum += __shfl_xor_sync(0xffffffffu, sum, off);
        float inv = 1.0f / sum;
        sc[h * 64 + l] = e0 * inv;
        sc[h * 64 + 32 + l] = e1 * inv;
    }
    __syncthreads();

    {
        const int h = tid >> 6;
        const __half* vp = V + (size_t)st * HID + tid;
        const float* ap = &sc[h * 64];
        float o = 0.0f;
        int m = 0;
        for (; m + 4 <= len; m += 4) {
            float a0 = ap[m], a1 = ap[m + 1], a2 = ap[m + 2], a3 = ap[m + 3];
            float v0 = __half2float(vp[(size_t)m * HID]);
            float v1 = __half2float(vp[(size_t)(m + 1) * HID]);
            float v2 = __half2float(vp[(size_t)(m + 2) * HID]);
            float v3 = __half2float(vp[(size_t)(m + 3) * HID]);
            o = fmaf(a0, v0, o); o = fmaf(a1, v1, o);
            o = fmaf(a2, v2, o); o = fmaf(a3, v3, o);
        }
        for (; m < len; m++) o = fmaf(ap[m], __half2float(vp[(size_t)m * HID]), o);
        O[(size_t)b * HID + tid] = __float2half(o);
    }
}

// ======================= launch =======================
extern "C" void kernel_launch(void* const* d_in, const int* in_sizes, int n_in,
                              void* d_out, int out_size)
{
    const float* enc = (const float*)d_in[0];
    const float* soc = (const float*)d_in[1];
    const float* Wq = (const float*)d_in[2];
    const float* bq = (const float*)d_in[3];
    const float* Wk = (const float*)d_in[4];
    const float* bk = (const float*)d_in[5];
    const float* Wv = (const float*)d_in[6];
    const float* bv = (const float*)d_in[7];
    const float* Wf = (const float*)d_in[8];
    const float* bf = (const float*)d_in[9];
    const int* st = (const int*)d_in[10];
    const int* en = (const int*)d_in[11];
    float* out = (float*)d_out;

    float* qp;
    __half *kp, *vp, *op;
    cudaGetSymbolAddress((void**)&qp, g_Q);
    cudaGetSymbolAddress((void**)&kp, g_K);
    cudaGetSymbolAddress((void**)&vp, g_V);
    cudaGetSymbolAddress((void**)&op, g_O);

    cudaFuncSetAttribute(kvq_mma, cudaFuncAttributeMaxDynamicSharedMemorySize, KV_SMEM);
    cudaFuncSetAttribute(fin_mma, cudaFuncAttributeMaxDynamicSharedMemorySize, FIN_SMEM);

    // coverage: flags -> compacted row indices
    zerofill<<<NTOT / 256, 256>>>();
    mark<<<128, 256>>>(st, en);
    compact<<<NTOT / 256, 256>>>();
    // weights -> fp16 (once)
    w2h<<<HID * HID / 256, 256>>>(Wk, Wv, Wq, Wf);
    // fused K,V,Q projections (KV gathered over covered rows)
    kvq_mma<<<NTOT / 128 + NB / 128, 256, KV_SMEM>>>(
        soc, enc, bk, bv, bq, kp, vp, qp);
    // attention (fp16 O out)
    attn3<<<NB, 256>>>(qp, kp, vp, st, en, op);
    // final projection via fp16 mma (32-row tiles)
    fin_mma<<<NB / 32, 256, FIN_SMEM>>>(op, bf, out);
}

// round 12
// speedup vs baseline: 6.5576x; 1.0231x over previous
#include <cuda_runtime.h>
#include <cuda_fp16.h>
#include <cstdint>

#define HID 256
#define NB 4096
#define NTOT 131072

// Scratch (allocation-free rule: __device__ globals)
__device__ float  g_Q[(size_t)NB * HID];
__device__ __half g_K[(size_t)NTOT * HID];
__device__ __half g_V[(size_t)NTOT * HID];
__device__ __half g_O[(size_t)NB * HID];
__device__ __half g_Wk16[HID * HID];
__device__ __half g_Wv16[HID * HID];
__device__ __half g_Wq16[HID * HID];
__device__ __half g_Wf16[HID * HID];
__device__ int    g_idx[NTOT];
__device__ unsigned char g_flag[NTOT];
__device__ int    g_count;

// ======================= helpers =======================
__device__ __forceinline__ void mma_f16(float* d, const uint32_t* a, const uint32_t* b) {
    asm volatile(
        "mma.sync.aligned.m16n8k16.row.col.f32.f16.f16.f32 "
        "{%0,%1,%2,%3},{%4,%5,%6,%7},{%8,%9},{%0,%1,%2,%3};"
        : "+f"(d[0]), "+f"(d[1]), "+f"(d[2]), "+f"(d[3])
        : "r"(a[0]), "r"(a[1]), "r"(a[2]), "r"(a[3]), "r"(b[0]), "r"(b[1]));
}
__device__ __forceinline__ uint32_t h2u(float lo, float hi) {
    __half2 h = __floats2half2_rn(lo, hi);
    return *(uint32_t*)&h;
}
__device__ __forceinline__ uint32_t smem_u32(const void* p) {
    return (uint32_t)__cvta_generic_to_shared(p);
}
__device__ __forceinline__ void ldsm_x4(uint32_t& r0, uint32_t& r1, uint32_t& r2, uint32_t& r3,
                                        uint32_t addr) {
    asm volatile("ldmatrix.sync.aligned.m8n8.x4.shared.b16 {%0,%1,%2,%3}, [%4];"
                 : "=r"(r0), "=r"(r1), "=r"(r2), "=r"(r3) : "r"(addr));
}
__device__ __forceinline__ void cpa16(uint32_t dst, const void* src) {
    asm volatile("cp.async.ca.shared.global [%0], [%1], 16;" :: "r"(dst), "l"(src));
}
__device__ __forceinline__ void cpa_commit() {
    asm volatile("cp.async.commit_group;" ::: "memory");
}
__device__ __forceinline__ void cpa_wait2() {
    asm volatile("cp.async.wait_group 2;" ::: "memory");
}
__device__ __forceinline__ void cpa_wait0() {
    asm volatile("cp.async.wait_all;" ::: "memory");
}

#define AST2 132
#define BST2 20
#define BBUF (128 * BST2)
#define KV_SMEM ((128 * AST2 + 4 * BBUF) * 4)
#define FIN_SMEM ((32 * AST2 + 4 * BBUF) * 4)

// ======== prep: zero flags/idx/count + weights fp32->fp16 (fused) ========
__global__ void __launch_bounds__(256) prep(
    const float* __restrict__ Wk, const float* __restrict__ Wv,
    const float* __restrict__ Wq, const float* __restrict__ Wf)
{
    const int i = blockIdx.x * 256 + threadIdx.x;    // grid 512 -> 131072
    g_idx[i] = 0;
    if (i < NTOT / 4) ((int*)g_flag)[i] = 0;
    if (i == 0) g_count = 0;
    if (i < HID * HID) {
        g_Wk16[i] = __float2half_rn(Wk[i]);
        g_Wv16[i] = __float2half_rn(Wv[i]);
        g_Wq16[i] = __float2half_rn(Wq[i]);
        g_Wf16[i] = __float2half_rn(Wf[i]);
    }
}

__global__ void __launch_bounds__(256) mark(const int* __restrict__ st,
                                            const int* __restrict__ en) {
    const int w = (blockIdx.x * 256 + threadIdx.x) >> 5;   // grid 128 -> 1024 warps
    const int lane = threadIdx.x & 31;
#pragma unroll
    for (int q = 0; q < 4; q++) {
        const int s = w * 4 + q;
        const int a = st[s], b = en[s];
        for (int r = a + lane; r < b; r += 32) g_flag[r] = 1;
    }
}

__global__ void __launch_bounds__(256) compact() {
    const int i = blockIdx.x * 256 + threadIdx.x;
    const int lane = threadIdx.x & 31;
    const int f = g_flag[i];
    const unsigned mask = __ballot_sync(0xffffffffu, f);
    int base = 0;
    if (lane == 0 && mask) base = atomicAdd(&g_count, __popc(mask));
    base = __shfl_sync(0xffffffffu, base, 0);
    if (f) g_idx[base + __popc(mask & ((1u << lane) - 1u))] = i;
}

// issue one B chunk (128 n-rows x 32 k, fp16) via cp.async into ring slot
__device__ __forceinline__ void issue_b(const __half* W16, int nh, int kc,
                                        uint32_t bufb32, int tid) {
#pragma unroll
    for (int r = 0; r < 2; r++) {
        const int task = tid + r * 256;
        const int n = task >> 2;
        const int s = task & 3;
        cpa16(bufb32 + (uint32_t)((n * BST2 + s * 4) * 4),
              W16 + (size_t)(nh * 128 + n) * HID + kc * 32 + s * 8);
    }
}

// ============ fused K+V+Q projections: gather-GEMM over covered rows ============
__global__ void __launch_bounds__(256, 2)
kvq_mma(const float* __restrict__ soc, const float* __restrict__ enc,
        const float* __restrict__ bk, const float* __restrict__ bv,
        const float* __restrict__ bq,
        __half* __restrict__ Kout, __half* __restrict__ Vout,
        float* __restrict__ Qout)
{
    extern __shared__ uint32_t sm32[];
    uint32_t* As = sm32;
    const uint32_t Abase = smem_u32(As);
    const uint32_t Bbase = Abase + 128 * AST2 * 4;

    const int tid = threadIdx.x;
    const int lane = tid & 31;
    const int wid = tid >> 5;
    const int wm = wid & 1;
    const int wn = wid >> 1;
    const int bm = blockIdx.x;
    const bool isQ = (bm >= NTOT / 128);
    const int rowblk = isQ ? (bm - NTOT / 128) : bm;
    const int ntc_total = isQ ? 16 : 32;
    const int gbase = rowblk * 128;

    if (!isQ && gbase >= g_count) return;

    const int arow = wm * 64 + (lane & 15);
    const int acol = (lane >> 4) << 2;
    const int brow = wn * 32 + ((lane >> 4) << 3) + (lane & 7);
    const int bcol = ((lane >> 3) & 1) << 2;

    const __half* WK16 = isQ ? g_Wq16 : g_Wk16;
    const __half* WV16 = isQ ? g_Wq16 : g_Wv16;
    issue_b(WK16, 0, 0, Bbase, tid);
    cpa_commit();
    issue_b(WK16, 0, 1, Bbase + BBUF * 4, tid);
    cpa_commit();

    // ---- stage A tile 128x256 -> fp16 (gathered rows for KV mode) ----
#pragma unroll
    for (int i = 0; i < 32; i++) {
        int idx = i * 256 + tid;
        int r = idx >> 6, c4 = (idx & 63) << 2;
        const size_t grow = isQ ? (size_t)(gbase + r) : (size_t)g_idx[gbase + r];
        const float* src = (isQ ? enc : soc) + grow * HID + c4;
        float4 v = *(const float4*)src;
        uint2 h;
        h.x = h2u(v.x, v.y);
        h.y = h2u(v.z, v.w);
        *(uint2*)&As[r * AST2 + (c4 >> 1)] = h;
    }
    __syncthreads();

    float acc[4][4][4];
#pragma unroll
    for (int i = 0; i < 4; i++)
#pragma unroll
        for (int j = 0; j < 4; j++)
#pragma unroll
            for (int t = 0; t < 4; t++) acc[i][j][t] = 0.0f;

    for (int tc = 0; tc < ntc_total; tc++) {
        const int p = tc >> 3;
        const int kc = tc & 7;

        uint32_t a0[4][4];
        {
            const int kb = kc * 16;
#pragma unroll
            for (int i = 0; i < 4; i++)
                ldsm_x4(a0[i][0], a0[i][1], a0[i][2], a0[i][3],
                        Abase + (uint32_t)(((arow + i * 16) * AST2 + kb + acol) * 4));
        }

        if (tc + 2 < ntc_total) {
            const int ntc = tc + 2;
            const int np = ntc >> 3, nkc = ntc & 7;
            const __half* W = (np < 2) ? WK16 : WV16;
            issue_b(W, np & 1, nkc, Bbase + (uint32_t)(((ntc) & 3) * BBUF * 4), tid);
        }
        cpa_commit();
        cpa_wait2();
        __syncthreads();

        const uint32_t Bb32 = Bbase + (uint32_t)((tc & 3) * BBUF * 4);

        // ks = 0
        {
            uint32_t b[4][2];
            ldsm_x4(b[0][0], b[0][1], b[1][0], b[1][1],
                    Bb32 + (uint32_t)((brow * BST2 + bcol) * 4));
            ldsm_x4(b[2][0], b[2][1], b[3][0], b[3][1],
                    Bb32 + (uint32_t)(((brow + 16) * BST2 + bcol) * 4));
#pragma unroll
            for (int i = 0; i < 4; i++)
#pragma unroll
                for (int j = 0; j < 4; j++) mma_f16(acc[i][j], a0[i], b[j]);
        }
        // ks = 1
        {
            const int kb = kc * 16 + 8;
            uint32_t a[4][4];
#pragma unroll
            for (int i = 0; i < 4; i++)
                ldsm_x4(a[i][0], a[i][1], a[i][2], a[i][3],
                        Abase + (uint32_t)(((arow + i * 16) * AST2 + kb + acol) * 4));
            uint32_t b[4][2];
            const int bk0 = 8 + bcol;
            ldsm_x4(b[0][0], b[0][1], b[1][0], b[1][1],
                    Bb32 + (uint32_t)((brow * BST2 + bk0) * 4));
            ldsm_x4(b[2][0], b[2][1], b[3][0], b[3][1],
                    Bb32 + (uint32_t)(((brow + 16) * BST2 + bk0) * 4));
#pragma unroll
            for (int i = 0; i < 4; i++)
#pragma unroll
                for (int j = 0; j < 4; j++) mma_f16(acc[i][j], a[i], b[j]);
        }

        if (kc == 7) {
            const int nh = p & 1;
            const int colw = nh * 128 + wn * 32 + (lane & 3) * 2;
            const int lrow = wm * 64 + (lane >> 2);
            if (isQ) {
#pragma unroll
                for (int j = 0; j < 4; j++) {
                    const float2 bb = *(const float2*)&bq[colw + j * 8];
#pragma unroll
                    for (int i = 0; i < 4; i++) {
                        const size_t r0 = (size_t)gbase + lrow + i * 16;
                        float2 o0, o1;
                        o0.x = fmaxf(acc[i][j][0] + bb.x, 0.0f) * 0.0625f;
                        o0.y = fmaxf(acc[i][j][1] + bb.y, 0.0f) * 0.0625f;
                        o1.x = fmaxf(acc[i][j][2] + bb.x, 0.0f) * 0.0625f;
                        o1.y = fmaxf(acc[i][j][3] + bb.y, 0.0f) * 0.0625f;
                        *(float2*)&Qout[r0 * HID + colw + j * 8] = o0;
                        *(float2*)&Qout[(r0 + 8) * HID + colw + j * 8] = o1;
#pragma unroll
                        for (int t = 0; t < 4; t++) acc[i][j][t] = 0.0f;
                    }
                }
            } else {
                const float* bias = (p < 2) ? bk : bv;
                __half* Cout = (p < 2) ? Kout : Vout;
#pragma unroll
                for (int i = 0; i < 4; i++) {
                    const size_t r0 = (size_t)g_idx[gbase + lrow + i * 16];
                    const size_t r1 = (size_t)g_idx[gbase + lrow + i * 16 + 8];
#pragma unroll
                    for (int j = 0; j < 4; j++) {
                        const float2 bb = *(const float2*)&bias[colw + j * 8];
                        uint32_t u0 = h2u(fmaxf(acc[i][j][0] + bb.x, 0.0f),
                                          fmaxf(acc[i][j][1] + bb.y, 0.0f));
                        uint32_t u1 = h2u(fmaxf(acc[i][j][2] + bb.x, 0.0f),
                                          fmaxf(acc[i][j][3] + bb.y, 0.0f));
                        *(uint32_t*)&Cout[r0 * HID + colw + j * 8] = u0;
                        *(uint32_t*)&Cout[r1 * HID + colw + j * 8] = u1;
#pragma unroll
                        for (int t = 0; t < 4; t++) acc[i][j][t] = 0.0f;
                    }
                }
            }
        }
    }
}

// ============ final projection: 32-row tiles, 128 CTAs (mma.sync fp16) ============
__global__ void __launch_bounds__(256, 2)
fin_mma(const __half* __restrict__ O, const float* __restrict__ bf,
        float* __restrict__ out)
{
    extern __shared__ uint32_t sm32[];
    uint32_t* As = sm32;
    const uint32_t Abase = smem_u32(As);
    const uint32_t Bbase = Abase + 32 * AST2 * 4;

    const int tid = threadIdx.x;
    const int lane = tid & 31;
    const int wid = tid >> 5;
    const int wm = wid & 1;
    const int wn = wid >> 1;
    const int bm = blockIdx.x;

    const int arow = wm * 16 + (lane & 15);
    const int acol = (lane >> 4) << 2;
    const int brow = wn * 32 + ((lane >> 4) << 3) + (lane & 7);
    const int bcol = ((lane >> 3) & 1) << 2;

    issue_b(g_Wf16, 0, 0, Bbase, tid);
    cpa_commit();
    issue_b(g_Wf16, 0, 1, Bbase + BBUF * 4, tid);
    cpa_commit();

    const __half* Ab = O + (size_t)bm * 32 * HID;
#pragma unroll
    for (int i = 0; i < 4; i++) {
        int idx = i * 256 + tid;
        int r = idx >> 5, c2 = (idx & 31) * 4;
        uint4 v = *(const uint4*)(Ab + (size_t)r * HID + c2 * 2);
        *(uint4*)&As[r * AST2 + c2] = v;
    }
    __syncthreads();

    float acc[4][4];
#pragma unroll
    for (int j = 0; j < 4; j++)
#pragma unroll
        for (int t = 0; t < 4; t++) acc[j][t] = 0.0f;

    for (int tc = 0; tc < 16; tc++) {
        const int p = tc >> 3;
        const int kc = tc & 7;

        uint32_t a0[4];
        ldsm_x4(a0[0], a0[1], a0[2], a0[3],
                Abase + (uint32_t)((arow * AST2 + kc * 16 + acol) * 4));

        if (tc + 2 < 16) {
            const int ntc = tc + 2;
            issue_b(g_Wf16, (ntc >> 3) & 1, ntc & 7,
                    Bbase + (uint32_t)((ntc & 3) * BBUF * 4), tid);
        }
        cpa_commit();
        cpa_wait2();
        __syncthreads();

        const uint32_t Bb32 = Bbase + (uint32_t)((tc & 3) * BBUF * 4);
        {
            uint32_t b[4][2];
            ldsm_x4(b[0][0], b[0][1], b[1][0], b[1][1],
                    Bb32 + (uint32_t)((brow * BST2 + bcol) * 4));
            ldsm_x4(b[2][0], b[2][1], b[3][0], b[3][1],
                    Bb32 + (uint32_t)(((brow + 16) * BST2 + bcol) * 4));
#pragma unroll
            for (int j = 0; j < 4; j++) mma_f16(acc[j], a0, b[j]);
        }
        {
            uint32_t a[4];
            ldsm_x4(a[0], a[1], a[2], a[3],
                    Abase + (uint32_t)((arow * AST2 + kc * 16 + 8 + acol) * 4));
            uint32_t b[4][2];
            const int bk0 = 8 + bcol;
            ldsm_x4(b[0][0], b[0][1], b[1][0], b[1][1],
                    Bb32 + (uint32_t)((brow * BST2 + bk0) * 4));
            ldsm_x4(b[2][0], b[2][1], b[3][0], b[3][1],
                    Bb32 + (uint32_t)(((brow + 16) * BST2 + bk0) * 4));
#pragma unroll
            for (int j = 0; j < 4; j++) mma_f16(acc[j], a, b[j]);
        }

        if (kc == 7) {
            const int nh = p & 1;
            const int colw = nh * 128 + wn * 32 + (lane & 3) * 2;
            const size_t rowb = (size_t)bm * 32 + wm * 16 + (lane >> 2);
#pragma unroll
            for (int j = 0; j < 4; j++) {
                const float2 bb = *(const float2*)&bf[colw + j * 8];
                float2 o0, o1;
                o0.x = acc[j][0] + bb.x;
                o0.y = acc[j][1] + bb.y;
                o1.x = acc[j][2] + bb.x;
                o1.y = acc[j][3] + bb.y;
                *(float2*)&out[rowb * HID + colw + j * 8] = o0;
                *(float2*)&out[(rowb + 8) * HID + colw + j * 8] = o1;
#pragma unroll
                for (int t = 0; t < 4; t++) acc[j][t] = 0.0f;
            }
        }
    }
}

// ===== attention: 1 CTA / sample; V prefetched to smem via cp.async =====
__global__ __launch_bounds__(256) void attn4(
    const float* __restrict__ Q, const __half* __restrict__ K,
    const __half* __restrict__ V, const int* __restrict__ starts,
    const int* __restrict__ ends, __half* __restrict__ O)
{
    __shared__ __half Vs[64 * HID];    // 32 KB
    __shared__ float qs[256];
    __shared__ float sc[256];

    const int tid = threadIdx.x;
    const int lane = tid & 31;
    const int wid = tid >> 5;
    const int b = blockIdx.x;
    const int st = starts[b];
    const int len = ends[b] - st;      // 1..64

    // ---- issue V segment prefetch (len rows x 512 B) ----
    {
        const uint32_t vb = smem_u32(Vs);
        const int nch = len * 32;       // 16B chunks
        for (int c = tid; c < nch; c += 256)
            cpa16(vb + (uint32_t)c * 16, (const char*)(V + (size_t)st * HID) + (size_t)c * 16);
        cpa_commit();
    }

    qs[tid] = Q[(size_t)b * HID + tid];
    sc[tid] = -1e30f;
    __syncthreads();

    float4 q0 = *(const float4*)&qs[lane * 8];
    float4 q1 = *(const float4*)&qs[lane * 8 + 4];
    const int head = lane >> 3;

    // scores (K from gmem, overlaps with V prefetch)
#pragma unroll
    for (int rr = 0; rr < 8; rr++) {
        const int m = rr * 8 + wid;
        if (m < len) {
            uint4 raw = *(const uint4*)(K + (size_t)(st + m) * HID + lane * 8);
            float2 f0 = __half22float2(*(__half2*)&raw.x);
            float2 f1 = __half22float2(*(__half2*)&raw.y);
            float2 f2 = __half22float2(*(__half2*)&raw.z);
            float2 f3 = __half22float2(*(__half2*)&raw.w);
            float p = q0.x * f0.x + q0.y * f0.y + q0.z * f1.x + q0.w * f1.y
                    + q1.x * f2.x + q1.y * f2.y + q1.z * f3.x + q1.w * f3.y;
            p += __shfl_down_sync(0xffffffffu, p, 4);
            p += __shfl_down_sync(0xffffffffu, p, 2);
            p += __shfl_down_sync(0xffffffffu, p, 1);
            if ((lane & 7) == 0) sc[head * 64 + m] = p;
        }
    }
    __syncthreads();

    // softmax
    if (tid < 128) {
        const int h = tid >> 5, l = tid & 31;
        float v0 = sc[h * 64 + l];
        float v1 = sc[h * 64 + 32 + l];
        float mx = fmaxf(v0, v1);
#pragma unroll
        for (int off = 16; off > 0; off >>= 1)
            mx = fmaxf(mx, __shfl_xor_sync(0xffffffffu, mx, off));
        float e0 = __expf(v0 - mx);
        float e1 = __expf(v1 - mx);
        float sum = e0 + e1;
#pragma unroll
        for (int off = 16; off > 0; off >>= 1)
            sum += __shfl_xor_sync(0xffffffffu, sum, off);
        float inv = 1.0f / sum;
        sc[h * 64 + l] = e0 * inv;
        sc[h * 64 + 32 + l] = e1 * inv;
    }
    cpa_wait0();
    __syncthreads();

    // out: thread = output channel, V from smem (29-cyc LDS)
    {
        const int h = tid >> 6;
        const __half* vp = Vs + tid;
        const float* ap = &sc[h * 64];
        float o = 0.0f;
        int m = 0;
        for (; m + 4 <= len; m += 4) {
            float a0 = ap[m], a1 = ap[m + 1], a2 = ap[m + 2], a3 = ap[m + 3];
            float v0 = __half2float(vp[(m) * HID]);
            float v1 = __half2float(vp[(m + 1) * HID]);
            float v2 = __half2float(vp[(m + 2) * HID]);
            float v3 = __half2float(vp[(m + 3) * HID]);
            o = fmaf(a0, v0, o); o = fmaf(a1, v1, o);
            o = fmaf(a2, v2, o); o = fmaf(a3, v3, o);
        }
        for (; m < len; m++) o = fmaf(ap[m], __half2float(vp[m * HID]), o);
        O[(size_t)b * HID + tid] = __float2half(o);
    }
}

// ======================= launch =======================
extern "C" void kernel_launch(void* const* d_in, const int* in_sizes, int n_in,
                              void* d_out, int out_size)
{
    const float* enc = (const float*)d_in[0];
    const float* soc = (const float*)d_in[1];
    const float* Wq = (const float*)d_in[2];
    const float* bq = (const float*)d_in[3];
    const float* Wk = (const float*)d_in[4];
    const float* bk = (const float*)d_in[5];
    const float* Wv = (const float*)d_in[6];
    const float* bv = (const float*)d_in[7];
    const float* Wf = (const float*)d_in[8];
    const float* bf = (const float*)d_in[9];
    const int* st = (const int*)d_in[10];
    const int* en = (const int*)d_in[11];
    float* out = (float*)d_out;

    float* qp;
    __half *kp, *vp, *op;
    cudaGetSymbolAddress((void**)&qp, g_Q);
    cudaGetSymbolAddress((void**)&kp, g_K);
    cudaGetSymbolAddress((void**)&vp, g_V);
    cudaGetSymbolAddress((void**)&op, g_O);

    cudaFuncSetAttribute(kvq_mma, cudaFuncAttributeMaxDynamicSharedMemorySize, KV_SMEM);
    cudaFuncSetAttribute(fin_mma, cudaFuncAttributeMaxDynamicSharedMemorySize, FIN_SMEM);

    // prep: zero coverage state + convert weights (fused)
    prep<<<NTOT / 256, 256>>>(Wk, Wv, Wq, Wf);
    mark<<<128, 256>>>(st, en);
    compact<<<NTOT / 256, 256>>>();
    // fused K,V,Q projections (KV gathered over covered rows)
    kvq_mma<<<NTOT / 128 + NB / 128, 256, KV_SMEM>>>(
        soc, enc, bk, bv, bq, kp, vp, qp);
    // attention (V prefetched to smem)
    attn4<<<NB, 256>>>(qp, kp, vp, st, en, op);
    // final projection via fp16 mma (32-row tiles)
    fin_mma<<<NB / 32, 256, FIN_SMEM>>>(op, bf, out);
}